// round 2
// baseline (speedup 1.0000x reference)
#include <cuda_runtime.h>
#include <cstdint>

// Problem constants
#define BATCH   4
#define SEQ     1024
#define EMB     1024
#define HEADS   16
#define HDIM    64
#define MROWS   (BATCH * SEQ)      // 4096

// ---------------- scratch (static device allocations are allowed) ----------
__device__ float g_Q[MROWS * EMB];
__device__ float g_K[MROWS * EMB];
__device__ float g_V[MROWS * EMB];
__device__ float g_Z[MROWS * EMB];

// ---------------- 128x128x16 fp32 GEMM body: C = A@B + bias ----------------
// A: [4096,1024] row-major, B: [1024,1024] row-major, C: [4096,1024] row-major
__device__ __forceinline__ void sgemm_body(const float* __restrict__ A,
                                           const float* __restrict__ B,
                                           const float* __restrict__ bias,
                                           float* __restrict__ C)
{
    __shared__ float As[16][128];   // As[k][m]
    __shared__ float Bs[16][128];   // Bs[k][n]

    const int tid = threadIdx.x;          // 256 threads
    const int tm  = tid >> 4;             // 0..15
    const int tn  = tid & 15;             // 0..15
    const int row0 = blockIdx.y * 128 + tm * 8;
    const int col0 = blockIdx.x * 128 + tn * 8;

    float acc[8][8];
#pragma unroll
    for (int i = 0; i < 8; ++i)
#pragma unroll
        for (int j = 0; j < 8; ++j) acc[i][j] = 0.f;

    const int arow_base = blockIdx.y * 128;
    const int bcol_base = blockIdx.x * 128;

    for (int kt = 0; kt < EMB / 16; ++kt) {
        const int k0 = kt * 16;
        // load A tile: 128 rows x 16 cols = 512 float4
#pragma unroll
        for (int it = 0; it < 2; ++it) {
            int idx = tid + it * 256;
            int r  = idx >> 2;
            int c4 = (idx & 3) * 4;
            float4 a4 = *(const float4*)(A + (size_t)(arow_base + r) * EMB + k0 + c4);
            As[c4 + 0][r] = a4.x;
            As[c4 + 1][r] = a4.y;
            As[c4 + 2][r] = a4.z;
            As[c4 + 3][r] = a4.w;
        }
        // load B tile: 16 rows x 128 cols = 512 float4
#pragma unroll
        for (int it = 0; it < 2; ++it) {
            int idx = tid + it * 256;
            int r = idx >> 5;
            int c = (idx & 31) * 4;
            float4 b4 = *(const float4*)(B + (size_t)(k0 + r) * EMB + bcol_base + c);
            *(float4*)&Bs[r][c] = b4;
        }
        __syncthreads();

#pragma unroll
        for (int k = 0; k < 16; ++k) {
            float4 a0 = *(const float4*)&As[k][tm * 8];
            float4 a1 = *(const float4*)&As[k][tm * 8 + 4];
            float4 b0 = *(const float4*)&Bs[k][tn * 8];
            float4 b1 = *(const float4*)&Bs[k][tn * 8 + 4];
            float av[8] = {a0.x, a0.y, a0.z, a0.w, a1.x, a1.y, a1.z, a1.w};
            float bv[8] = {b0.x, b0.y, b0.z, b0.w, b1.x, b1.y, b1.z, b1.w};
#pragma unroll
            for (int i = 0; i < 8; ++i)
#pragma unroll
                for (int j = 0; j < 8; ++j)
                    acc[i][j] = fmaf(av[i], bv[j], acc[i][j]);
        }
        __syncthreads();
    }

    // epilogue with bias
    float bv[8];
#pragma unroll
    for (int j = 0; j < 8; ++j) bv[j] = bias[col0 + j];
#pragma unroll
    for (int i = 0; i < 8; ++i) {
        float4 o0 = make_float4(acc[i][0] + bv[0], acc[i][1] + bv[1],
                                acc[i][2] + bv[2], acc[i][3] + bv[3]);
        float4 o1 = make_float4(acc[i][4] + bv[4], acc[i][5] + bv[5],
                                acc[i][6] + bv[6], acc[i][7] + bv[7]);
        *(float4*)(C + (size_t)(row0 + i) * EMB + col0)     = o0;
        *(float4*)(C + (size_t)(row0 + i) * EMB + col0 + 4) = o1;
    }
}

// Fused QKV projection: gridDim.z = 3 selects (Wq,bq,Q) / (Wk,bk,K) / (Wv,bv,V)
__global__ __launch_bounds__(256) void qkv_gemm_kernel(
    const float* __restrict__ X,
    const float* __restrict__ Wq, const float* __restrict__ Wk, const float* __restrict__ Wv,
    const float* __restrict__ bq, const float* __restrict__ bk, const float* __restrict__ bv)
{
    const float* W; const float* bias; float* out;
    if (blockIdx.z == 0)      { W = Wq; bias = bq; out = g_Q; }
    else if (blockIdx.z == 1) { W = Wk; bias = bk; out = g_K; }
    else                      { W = Wv; bias = bv; out = g_V; }
    sgemm_body(X, W, bias, out);
}

__global__ __launch_bounds__(256) void out_gemm_kernel(
    const float* __restrict__ Wo, const float* __restrict__ bo,
    float* __restrict__ out)
{
    sgemm_body(g_Z, Wo, bo, out);
}

// ---------------- Flash attention (fp32, causal) ----------------
// Q/K/V layout: [B*S, E] row-major; head h occupies cols [h*64, h*64+64)
// Z layout: [B, H, S, Dh] contiguous
#define PAD 68   // row stride in smem (float4-aligned, conflict-light)

__global__ __launch_bounds__(128) void attn_kernel(
    const float* __restrict__ Q, const float* __restrict__ K,
    const float* __restrict__ V, float* __restrict__ Z)
{
    extern __shared__ float sm[];
    float* Qs   = sm;                 // [64][PAD]  Qs[r][d]
    float* KTs  = Qs  + 64 * PAD;     // [64][PAD]  KTs[d][c]  (K transposed)
    float* Vs   = KTs + 64 * PAD;     // [64][PAD]  Vs[kk][c]
    float* Ps   = Vs  + 64 * PAD;     // [64][PAD]  Ps[r][c]
    float* red  = Ps  + 64 * PAD;     // [64][8]
    float* mrow = red + 64 * 8;       // [64]
    float* lrow = mrow + 64;          // [64]
    float* arow = lrow + 64;          // [64]

    const int tid = threadIdx.x;      // 128 threads
    const int tx  = tid & 7;          // 0..7  -> 8 cols of 8
    const int ty  = tid >> 3;         // 0..15 -> 16 rows of 4
    const int r0  = ty * 4;
    const int c0  = tx * 8;

    const int qb = blockIdx.x;        // query tile 0..15
    const int bh = blockIdx.y;        // 0..63
    const int b  = bh >> 4;
    const int h  = bh & 15;

    const size_t base = (size_t)b * SEQ * EMB + (size_t)h * HDIM; // + s*EMB + d

    // load Q tile (64 rows x 64 cols), 1024 float4 / 128 threads
    for (int i = tid; i < 64 * 16; i += 128) {
        int r  = i >> 4;
        int c4 = (i & 15) * 4;
        float4 v = *(const float4*)(Q + base + (size_t)(qb * 64 + r) * EMB + c4);
        Qs[r * PAD + c4 + 0] = v.x;
        Qs[r * PAD + c4 + 1] = v.y;
        Qs[r * PAD + c4 + 2] = v.z;
        Qs[r * PAD + c4 + 3] = v.w;
    }
    if (tid < 64) { mrow[tid] = -1e30f; lrow[tid] = 0.f; }

    float o[4][8];
#pragma unroll
    for (int i = 0; i < 4; ++i)
#pragma unroll
        for (int j = 0; j < 8; ++j) o[i][j] = 0.f;

    __syncthreads();

    for (int jb = 0; jb <= qb; ++jb) {
        // load K (transposed) and V tiles
        for (int i = tid; i < 64 * 16; i += 128) {
            int r  = i >> 4;
            int c4 = (i & 15) * 4;
            const size_t goff = base + (size_t)(jb * 64 + r) * EMB + c4;
            float4 kv = *(const float4*)(K + goff);
            KTs[(c4 + 0) * PAD + r] = kv.x;
            KTs[(c4 + 1) * PAD + r] = kv.y;
            KTs[(c4 + 2) * PAD + r] = kv.z;
            KTs[(c4 + 3) * PAD + r] = kv.w;
            float4 vv = *(const float4*)(V + goff);
            *(float4*)&Vs[r * PAD + c4] = vv;
        }
        __syncthreads();

        // S = Q @ K^T  (micro-tile 4x8 per thread)
        float s[4][8];
#pragma unroll
        for (int i = 0; i < 4; ++i)
#pragma unroll
            for (int j = 0; j < 8; ++j) s[i][j] = 0.f;

#pragma unroll 8
        for (int d = 0; d < 64; ++d) {
            float qv[4];
#pragma unroll
            for (int i = 0; i < 4; ++i) qv[i] = Qs[(r0 + i) * PAD + d];
            float4 k0 = *(const float4*)&KTs[d * PAD + c0];
            float4 k1 = *(const float4*)&KTs[d * PAD + c0 + 4];
            float kv[8] = {k0.x, k0.y, k0.z, k0.w, k1.x, k1.y, k1.z, k1.w};
#pragma unroll
            for (int i = 0; i < 4; ++i)
#pragma unroll
                for (int j = 0; j < 8; ++j)
                    s[i][j] = fmaf(qv[i], kv[j], s[i][j]);
        }

        // scale by 1/HEADS^0.25 = 0.5 exactly; causal mask on the diagonal tile
        if (jb == qb) {
#pragma unroll
            for (int i = 0; i < 4; ++i) {
                int gi = r0 + i;
#pragma unroll
                for (int j = 0; j < 8; ++j) {
                    int gj = c0 + j;
                    s[i][j] = (gj <= gi) ? s[i][j] * 0.5f : -1e30f;
                }
            }
        } else {
#pragma unroll
            for (int i = 0; i < 4; ++i)
#pragma unroll
                for (int j = 0; j < 8; ++j) s[i][j] *= 0.5f;
        }

        // row-max partials
#pragma unroll
        for (int i = 0; i < 4; ++i) {
            float pm = s[i][0];
#pragma unroll
            for (int j = 1; j < 8; ++j) pm = fmaxf(pm, s[i][j]);
            red[(r0 + i) * 8 + tx] = pm;
        }
        __syncthreads();

        if (tid < 64) {
            float mo = mrow[tid], mx = mo;
#pragma unroll
            for (int t = 0; t < 8; ++t) mx = fmaxf(mx, red[tid * 8 + t]);
            mrow[tid] = mx;
            float a = __expf(mo - mx);
            arow[tid] = a;
            lrow[tid] *= a;
        }
        __syncthreads();

        // P = exp(S - m), partial sums, rescale O
#pragma unroll
        for (int i = 0; i < 4; ++i) {
            float m  = mrow[r0 + i];
            float ps = 0.f;
#pragma unroll
            for (int j = 0; j < 8; ++j) {
                float p = __expf(s[i][j] - m);
                Ps[(r0 + i) * PAD + c0 + j] = p;
                ps += p;
            }
            red[(r0 + i) * 8 + tx] = ps;
            float a = arow[r0 + i];
#pragma unroll
            for (int j = 0; j < 8; ++j) o[i][j] *= a;
        }
        __syncthreads();

        if (tid < 64) {
            float ss = 0.f;
#pragma unroll
            for (int t = 0; t < 8; ++t) ss += red[tid * 8 + t];
            lrow[tid] += ss;
        }

        // O += P @ V
#pragma unroll 8
        for (int kk = 0; kk < 64; ++kk) {
            float pv[4];
#pragma unroll
            for (int i = 0; i < 4; ++i) pv[i] = Ps[(r0 + i) * PAD + kk];
            float4 v0 = *(const float4*)&Vs[kk * PAD + c0];
            float4 v1 = *(const float4*)&Vs[kk * PAD + c0 + 4];
            float vv[8] = {v0.x, v0.y, v0.z, v0.w, v1.x, v1.y, v1.z, v1.w};
#pragma unroll
            for (int i = 0; i < 4; ++i)
#pragma unroll
                for (int j = 0; j < 8; ++j)
                    o[i][j] = fmaf(pv[i], vv[j], o[i][j]);
        }
        __syncthreads();
    }

    // normalize + write Z[B,H,S,Dh]
    const size_t zbase = ((size_t)bh * SEQ + (size_t)qb * 64) * HDIM;
#pragma unroll
    for (int i = 0; i < 4; ++i) {
        float inv = 1.f / lrow[r0 + i];
        float4 o0 = make_float4(o[i][0] * inv, o[i][1] * inv, o[i][2] * inv, o[i][3] * inv);
        float4 o1 = make_float4(o[i][4] * inv, o[i][5] * inv, o[i][6] * inv, o[i][7] * inv);
        *(float4*)(g_Z + zbase + (size_t)(r0 + i) * HDIM + c0)     = o0;
        *(float4*)(g_Z + zbase + (size_t)(r0 + i) * HDIM + c0 + 4) = o1;
    }
    (void)Z;
}

// ---------------- launch ----------------
extern "C" void kernel_launch(void* const* d_in, const int* in_sizes, int n_in,
                              void* d_out, int out_size)
{
    // input order: inputs, mask, wq, bq, wk, bk, wv, bv, wo, bo
    const float* X  = (const float*)d_in[0];
    const float* wq = (const float*)d_in[2];
    const float* bq = (const float*)d_in[3];
    const float* wk = (const float*)d_in[4];
    const float* bk = (const float*)d_in[5];
    const float* wv = (const float*)d_in[6];
    const float* bv = (const float*)d_in[7];
    const float* wo = (const float*)d_in[8];
    const float* bo = (const float*)d_in[9];
    float* out = (float*)d_out;

    float *Qp, *Kp, *Vp, *Zp;
    cudaGetSymbolAddress((void**)&Qp, g_Q);
    cudaGetSymbolAddress((void**)&Kp, g_K);
    cudaGetSymbolAddress((void**)&Vp, g_V);
    cudaGetSymbolAddress((void**)&Zp, g_Z);

    const int attn_smem = (4 * 64 * PAD + 64 * 8 + 3 * 64) * (int)sizeof(float);
    cudaFuncSetAttribute(attn_kernel, cudaFuncAttributeMaxDynamicSharedMemorySize, attn_smem);

    // QKV projections (fused into one launch, z selects which)
    qkv_gemm_kernel<<<dim3(EMB / 128, MROWS / 128, 3), 256>>>(X, wq, wk, wv, bq, bk, bv);

    // causal flash attention
    attn_kernel<<<dim3(SEQ / 64, BATCH * HEADS), 128, attn_smem>>>(Qp, Kp, Vp, Zp);

    // output projection
    out_gemm_kernel<<<dim3(EMB / 128, MROWS / 128), 256>>>(wo, bo, out);

    (void)in_sizes; (void)n_in; (void)out_size;
}

// round 4
// speedup vs baseline: 1.5013x; 1.5013x over previous
#include <cuda_runtime.h>
#include <cuda_bf16.h>
#include <cstdint>

// Problem constants
#define BATCH   4
#define SEQ     1024
#define EMB     1024
#define HEADS   16
#define HDIM    64
#define MROWS   (BATCH * SEQ)      // 4096

// ---------------- scratch ----------------
__device__ float g_Q[MROWS * EMB];
__device__ float g_K[MROWS * EMB];
__device__ float g_V[MROWS * EMB];
__device__ float g_Z[MROWS * EMB];

__device__ __nv_bfloat16 g_Xhi[MROWS * EMB];
__device__ __nv_bfloat16 g_Xlo[MROWS * EMB];
__device__ __nv_bfloat16 g_Zhi[MROWS * EMB];
__device__ __nv_bfloat16 g_Zlo[MROWS * EMB];
// 4 weight matrices, transposed to [N,K] K-major: order wq, wk, wv, wo
__device__ __nv_bfloat16 g_Whi[4 * EMB * EMB];
__device__ __nv_bfloat16 g_Wlo[4 * EMB * EMB];

// ================= PTX helpers (sm_80+ subset only; NO tcgen05) =============
__device__ __forceinline__ uint32_t smem_u32(const void* p) {
    uint32_t a;
    asm("{ .reg .u64 t; cvta.to.shared.u64 t, %1; cvt.u32.u64 %0, t; }" : "=r"(a) : "l"(p));
    return a;
}

__device__ __forceinline__ void cp_async16(uint32_t saddr, const void* gaddr) {
    asm volatile("cp.async.cg.shared.global [%0], [%1], 16;" :: "r"(saddr), "l"(gaddr));
}
#define CP_COMMIT()  asm volatile("cp.async.commit_group;" ::: "memory")
template <int N>
__device__ __forceinline__ void cp_wait() {
    asm volatile("cp.async.wait_group %0;" :: "n"(N) : "memory");
}

__device__ __forceinline__ void ldmatrix_x4(uint32_t (&r)[4], uint32_t addr) {
    asm volatile("ldmatrix.sync.aligned.m8n8.x4.shared.b16 {%0,%1,%2,%3}, [%4];"
                 : "=r"(r[0]), "=r"(r[1]), "=r"(r[2]), "=r"(r[3]) : "r"(addr));
}

__device__ __forceinline__ void mma_16816(float (&d)[4], const uint32_t (&a)[4],
                                          uint32_t b0, uint32_t b1) {
    asm volatile(
        "mma.sync.aligned.m16n8k16.row.col.f32.bf16.bf16.f32 "
        "{%0,%1,%2,%3}, {%4,%5,%6,%7}, {%8,%9}, {%0,%1,%2,%3};"
        : "+f"(d[0]), "+f"(d[1]), "+f"(d[2]), "+f"(d[3])
        : "r"(a[0]), "r"(a[1]), "r"(a[2]), "r"(a[3]), "r"(b0), "r"(b1));
}

// ================= conversion kernels =================
__global__ __launch_bounds__(256) void cvt_split_kernel(
    const float* __restrict__ src, __nv_bfloat16* __restrict__ hi,
    __nv_bfloat16* __restrict__ lo)
{
    int i = blockIdx.x * blockDim.x + threadIdx.x;     // one float4 each
    float4 v = ((const float4*)src)[i];
    __nv_bfloat16 h0 = __float2bfloat16(v.x);
    __nv_bfloat16 h1 = __float2bfloat16(v.y);
    __nv_bfloat16 h2 = __float2bfloat16(v.z);
    __nv_bfloat16 h3 = __float2bfloat16(v.w);
    __nv_bfloat16 l0 = __float2bfloat16(v.x - __bfloat162float(h0));
    __nv_bfloat16 l1 = __float2bfloat16(v.y - __bfloat162float(h1));
    __nv_bfloat16 l2 = __float2bfloat16(v.z - __bfloat162float(h2));
    __nv_bfloat16 l3 = __float2bfloat16(v.w - __bfloat162float(h3));
    __nv_bfloat162 hp0 = __nv_bfloat162(h0, h1), hp1 = __nv_bfloat162(h2, h3);
    __nv_bfloat162 lp0 = __nv_bfloat162(l0, l1), lp1 = __nv_bfloat162(l2, l3);
    ((uint2*)hi)[i] = make_uint2(*(uint32_t*)&hp0, *(uint32_t*)&hp1);
    ((uint2*)lo)[i] = make_uint2(*(uint32_t*)&lp0, *(uint32_t*)&lp1);
}

// W [K,N] fp32 -> WT [N,K] hi/lo bf16 (transpose+split). z selects matrix.
__global__ __launch_bounds__(256) void cvt_splitT_kernel(
    const float* __restrict__ w0, const float* __restrict__ w1,
    const float* __restrict__ w2, const float* __restrict__ w3)
{
    __shared__ float t[32][33];
    const int z = blockIdx.z;
    const float* W = (z == 0) ? w0 : (z == 1) ? w1 : (z == 2) ? w2 : w3;
    __nv_bfloat16* hiT = g_Whi + (size_t)z * EMB * EMB;
    __nv_bfloat16* loT = g_Wlo + (size_t)z * EMB * EMB;
    const int bx = blockIdx.x * 32;   // N base
    const int by = blockIdx.y * 32;   // K base
    const int tx = threadIdx.x & 31;
    const int ty = threadIdx.x >> 5;  // 0..7
    for (int i = ty; i < 32; i += 8)
        t[i][tx] = W[(size_t)(by + i) * EMB + bx + tx];
    __syncthreads();
    for (int i = ty; i < 32; i += 8) {
        float v = t[tx][i];                               // W[by+tx][bx+i]
        __nv_bfloat16 h = __float2bfloat16(v);
        __nv_bfloat16 l = __float2bfloat16(v - __bfloat162float(h));
        hiT[(size_t)(bx + i) * EMB + by + tx] = h;        // WT[n][k]
        loT[(size_t)(bx + i) * EMB + by + tx] = l;
    }
}

// ================= HMMA bf16x3 GEMM =================
// C[4096,1024] = A@B + bias ; A hi/lo [M,K], BT hi/lo [N,K] K-major.
// CTA 128x128, BK=32, double-buffered cp.async, 8 warps of 64x32.
#define BK          32
#define NCHUNK      (EMB / BK)              // 32
#define SA          40                       // smem row stride (elems), conflict-free
#define SPLIT_BYTES (128 * SA * 2)          // 10240
#define STAGE_BYTES (4 * SPLIT_BYTES)       // 40960: Ahi, Alo, Bhi, Blo
#define GEMM_SMEM   (2 * STAGE_BYTES)       // 81920

__device__ __forceinline__ void load_stage_async(
    uint32_t smb, const __nv_bfloat16* __restrict__ Ahi, const __nv_bfloat16* __restrict__ Alo,
    const __nv_bfloat16* __restrict__ Bhi, const __nv_bfloat16* __restrict__ Blo,
    int mbase, int nbase, int k0, int buf, int tid)
{
    const __nv_bfloat16* gsrc[4] = {
        Ahi + (size_t)mbase * EMB + k0, Alo + (size_t)mbase * EMB + k0,
        Bhi + (size_t)nbase * EMB + k0, Blo + (size_t)nbase * EMB + k0 };
    const uint32_t sbase = smb + buf * STAGE_BYTES;
#pragma unroll
    for (int m = 0; m < 4; ++m) {
#pragma unroll
        for (int i = 0; i < 2; ++i) {
            int idx = tid + i * 256;          // 512 x 16B per matrix
            int r = idx >> 2, seg = idx & 3;
            uint32_t sa = sbase + m * SPLIT_BYTES + (r * SA + seg * 8) * 2;
            cp_async16(sa, gsrc[m] + (size_t)r * EMB + seg * 8);
        }
    }
}

__device__ __forceinline__ void gemm_body_bf16(
    const __nv_bfloat16* __restrict__ Ahi, const __nv_bfloat16* __restrict__ Alo,
    const __nv_bfloat16* __restrict__ Bhi, const __nv_bfloat16* __restrict__ Blo,
    const float* __restrict__ bias, float* __restrict__ C)
{
    extern __shared__ char sm[];
    const uint32_t smb = smem_u32(sm);
    const int tid  = threadIdx.x;          // 256 threads
    const int wid  = tid >> 5;
    const int lane = tid & 31;
    const int mbase = blockIdx.y * 128;
    const int nbase = blockIdx.x * 128;

    const int wm = (wid & 1) * 64;         // warp M offset (2 warps along M)
    const int wn = (wid >> 1) * 32;        // warp N offset (4 warps along N)

    float acc[4][4][4];
#pragma unroll
    for (int mi = 0; mi < 4; ++mi)
#pragma unroll
        for (int ni = 0; ni < 4; ++ni)
#pragma unroll
            for (int e = 0; e < 4; ++e) acc[mi][ni][e] = 0.f;

    // ldmatrix lane addressing (within a [rows][SA] bf16 split)
    const int a_row = (lane & 15);
    const int a_koff = (lane >> 4) * 8;
    const int b_row = (lane & 7) + ((lane >> 4) * 8);
    const int b_koff = ((lane >> 3) & 1) * 8;

    load_stage_async(smb, Ahi, Alo, Bhi, Blo, mbase, nbase, 0, 0, tid);
    CP_COMMIT();

    for (int ck = 0; ck < NCHUNK; ++ck) {
        const int buf = ck & 1;
        if (ck + 1 < NCHUNK) {
            load_stage_async(smb, Ahi, Alo, Bhi, Blo, mbase, nbase, (ck + 1) * BK, buf ^ 1, tid);
            CP_COMMIT();
            cp_wait<1>();
        } else {
            cp_wait<0>();
        }
        __syncthreads();

        const uint32_t sAhi = smb + buf * STAGE_BYTES;
        const uint32_t sAlo = sAhi + SPLIT_BYTES;
        const uint32_t sBhi = sAhi + 2 * SPLIT_BYTES;
        const uint32_t sBlo = sAhi + 3 * SPLIT_BYTES;

#pragma unroll
        for (int ks = 0; ks < 2; ++ks) {           // two k=16 steps per chunk
            const int k0 = ks * 16;
            uint32_t ahi[4][4], alo[4][4];
#pragma unroll
            for (int mi = 0; mi < 4; ++mi) {
                uint32_t off = ((wm + mi * 16 + a_row) * SA + k0 + a_koff) * 2;
                ldmatrix_x4(ahi[mi], sAhi + off);
                ldmatrix_x4(alo[mi], sAlo + off);
            }
            uint32_t bhi[2][4], blo[2][4];
#pragma unroll
            for (int bi = 0; bi < 2; ++bi) {
                uint32_t off = ((wn + bi * 16 + b_row) * SA + k0 + b_koff) * 2;
                ldmatrix_x4(bhi[bi], sBhi + off);
                ldmatrix_x4(blo[bi], sBlo + off);
            }
#pragma unroll
            for (int mi = 0; mi < 4; ++mi) {
#pragma unroll
                for (int ni = 0; ni < 4; ++ni) {
                    const int g = ni >> 1, h = (ni & 1) * 2;
                    mma_16816(acc[mi][ni], ahi[mi], bhi[g][h], bhi[g][h + 1]);
                    mma_16816(acc[mi][ni], ahi[mi], blo[g][h], blo[g][h + 1]);
                    mma_16816(acc[mi][ni], alo[mi], bhi[g][h], bhi[g][h + 1]);
                }
            }
        }
        __syncthreads();
    }

    // epilogue: fragment layout m16n8: lane -> (row = lane>>2, col = (lane&3)*2)
    const int fr = lane >> 2;
    const int fc = (lane & 3) * 2;
#pragma unroll
    for (int mi = 0; mi < 4; ++mi) {
#pragma unroll
        for (int ni = 0; ni < 4; ++ni) {
            const int col = nbase + wn + ni * 8 + fc;
            const float b0 = bias[col], b1 = bias[col + 1];
            const int row0 = mbase + wm + mi * 16 + fr;
            float* p0 = C + (size_t)row0 * EMB + col;
            float* p1 = C + (size_t)(row0 + 8) * EMB + col;
            p0[0] = acc[mi][ni][0] + b0;
            p0[1] = acc[mi][ni][1] + b1;
            p1[0] = acc[mi][ni][2] + b0;
            p1[1] = acc[mi][ni][3] + b1;
        }
    }
}

__global__ __launch_bounds__(256, 1)
void qkv_mma_kernel(const float* __restrict__ bq, const float* __restrict__ bk,
                    const float* __restrict__ bv)
{
    const int z = blockIdx.z;
    const __nv_bfloat16* Bh = g_Whi + (size_t)z * EMB * EMB;
    const __nv_bfloat16* Bl = g_Wlo + (size_t)z * EMB * EMB;
    const float* bias = (z == 0) ? bq : (z == 1) ? bk : bv;
    float* C = (z == 0) ? g_Q : (z == 1) ? g_K : g_V;
    gemm_body_bf16(g_Xhi, g_Xlo, Bh, Bl, bias, C);
}

__global__ __launch_bounds__(256, 1)
void out_mma_kernel(const float* __restrict__ bo, float* __restrict__ out)
{
    gemm_body_bf16(g_Zhi, g_Zlo, g_Whi + (size_t)3 * EMB * EMB,
                   g_Wlo + (size_t)3 * EMB * EMB, bo, out);
}

// ---------------- Flash attention (fp32, causal) — unchanged ----------------
#define PAD 68

__global__ __launch_bounds__(128) void attn_kernel(
    const float* __restrict__ Q, const float* __restrict__ K,
    const float* __restrict__ V)
{
    extern __shared__ float smf[];
    float* Qs   = smf;
    float* KTs  = Qs  + 64 * PAD;
    float* Vs   = KTs + 64 * PAD;
    float* Ps   = Vs  + 64 * PAD;
    float* red  = Ps  + 64 * PAD;
    float* mrow = red + 64 * 8;
    float* lrow = mrow + 64;
    float* arow = lrow + 64;

    const int tid = threadIdx.x;
    const int tx  = tid & 7;
    const int ty  = tid >> 3;
    const int r0  = ty * 4;
    const int c0  = tx * 8;

    const int qb = blockIdx.x;
    const int bh = blockIdx.y;
    const int b  = bh >> 4;
    const int h  = bh & 15;

    const size_t base = (size_t)b * SEQ * EMB + (size_t)h * HDIM;

    for (int i = tid; i < 64 * 16; i += 128) {
        int r  = i >> 4;
        int c4 = (i & 15) * 4;
        float4 v = *(const float4*)(Q + base + (size_t)(qb * 64 + r) * EMB + c4);
        Qs[r * PAD + c4 + 0] = v.x;
        Qs[r * PAD + c4 + 1] = v.y;
        Qs[r * PAD + c4 + 2] = v.z;
        Qs[r * PAD + c4 + 3] = v.w;
    }
    if (tid < 64) { mrow[tid] = -1e30f; lrow[tid] = 0.f; }

    float o[4][8];
#pragma unroll
    for (int i = 0; i < 4; ++i)
#pragma unroll
        for (int j = 0; j < 8; ++j) o[i][j] = 0.f;

    __syncthreads();

    for (int jb = 0; jb <= qb; ++jb) {
        for (int i = tid; i < 64 * 16; i += 128) {
            int r  = i >> 4;
            int c4 = (i & 15) * 4;
            const size_t goff = base + (size_t)(jb * 64 + r) * EMB + c4;
            float4 kv = *(const float4*)(K + goff);
            KTs[(c4 + 0) * PAD + r] = kv.x;
            KTs[(c4 + 1) * PAD + r] = kv.y;
            KTs[(c4 + 2) * PAD + r] = kv.z;
            KTs[(c4 + 3) * PAD + r] = kv.w;
            float4 vv = *(const float4*)(V + goff);
            *(float4*)&Vs[r * PAD + c4] = vv;
        }
        __syncthreads();

        float s[4][8];
#pragma unroll
        for (int i = 0; i < 4; ++i)
#pragma unroll
            for (int j = 0; j < 8; ++j) s[i][j] = 0.f;

#pragma unroll 8
        for (int d = 0; d < 64; ++d) {
            float qv[4];
#pragma unroll
            for (int i = 0; i < 4; ++i) qv[i] = Qs[(r0 + i) * PAD + d];
            float4 k0 = *(const float4*)&KTs[d * PAD + c0];
            float4 k1 = *(const float4*)&KTs[d * PAD + c0 + 4];
            float kv[8] = {k0.x, k0.y, k0.z, k0.w, k1.x, k1.y, k1.z, k1.w};
#pragma unroll
            for (int i = 0; i < 4; ++i)
#pragma unroll
                for (int j = 0; j < 8; ++j)
                    s[i][j] = fmaf(qv[i], kv[j], s[i][j]);
        }

        if (jb == qb) {
#pragma unroll
            for (int i = 0; i < 4; ++i) {
                int gi = r0 + i;
#pragma unroll
                for (int j = 0; j < 8; ++j) {
                    int gj = c0 + j;
                    s[i][j] = (gj <= gi) ? s[i][j] * 0.5f : -1e30f;
                }
            }
        } else {
#pragma unroll
            for (int i = 0; i < 4; ++i)
#pragma unroll
                for (int j = 0; j < 8; ++j) s[i][j] *= 0.5f;
        }

#pragma unroll
        for (int i = 0; i < 4; ++i) {
            float pm = s[i][0];
#pragma unroll
            for (int j = 1; j < 8; ++j) pm = fmaxf(pm, s[i][j]);
            red[(r0 + i) * 8 + tx] = pm;
        }
        __syncthreads();

        if (tid < 64) {
            float mo = mrow[tid], mx = mo;
#pragma unroll
            for (int t = 0; t < 8; ++t) mx = fmaxf(mx, red[tid * 8 + t]);
            mrow[tid] = mx;
            float a = __expf(mo - mx);
            arow[tid] = a;
            lrow[tid] *= a;
        }
        __syncthreads();

#pragma unroll
        for (int i = 0; i < 4; ++i) {
            float m  = mrow[r0 + i];
            float ps = 0.f;
#pragma unroll
            for (int j = 0; j < 8; ++j) {
                float p = __expf(s[i][j] - m);
                Ps[(r0 + i) * PAD + c0 + j] = p;
                ps += p;
            }
            red[(r0 + i) * 8 + tx] = ps;
            float a = arow[r0 + i];
#pragma unroll
            for (int j = 0; j < 8; ++j) o[i][j] *= a;
        }
        __syncthreads();

        if (tid < 64) {
            float ss = 0.f;
#pragma unroll
            for (int t = 0; t < 8; ++t) ss += red[tid * 8 + t];
            lrow[tid] += ss;
        }

#pragma unroll 8
        for (int kk = 0; kk < 64; ++kk) {
            float pv[4];
#pragma unroll
            for (int i = 0; i < 4; ++i) pv[i] = Ps[(r0 + i) * PAD + kk];
            float4 v0 = *(const float4*)&Vs[kk * PAD + c0];
            float4 v1 = *(const float4*)&Vs[kk * PAD + c0 + 4];
            float vv[8] = {v0.x, v0.y, v0.z, v0.w, v1.x, v1.y, v1.z, v1.w};
#pragma unroll
            for (int i = 0; i < 4; ++i)
#pragma unroll
                for (int j = 0; j < 8; ++j)
                    o[i][j] = fmaf(pv[i], vv[j], o[i][j]);
        }
        __syncthreads();
    }

    const size_t zbase = ((size_t)bh * SEQ + (size_t)qb * 64) * HDIM;
#pragma unroll
    for (int i = 0; i < 4; ++i) {
        float inv = 1.f / lrow[r0 + i];
        float4 o0 = make_float4(o[i][0] * inv, o[i][1] * inv, o[i][2] * inv, o[i][3] * inv);
        float4 o1 = make_float4(o[i][4] * inv, o[i][5] * inv, o[i][6] * inv, o[i][7] * inv);
        *(float4*)(g_Z + zbase + (size_t)(r0 + i) * HDIM + c0)     = o0;
        *(float4*)(g_Z + zbase + (size_t)(r0 + i) * HDIM + c0 + 4) = o1;
    }
}

// ---------------- launch ----------------
extern "C" void kernel_launch(void* const* d_in, const int* in_sizes, int n_in,
                              void* d_out, int out_size)
{
    const float* X  = (const float*)d_in[0];
    const float* wq = (const float*)d_in[2];
    const float* bq = (const float*)d_in[3];
    const float* wk = (const float*)d_in[4];
    const float* bk = (const float*)d_in[5];
    const float* wv = (const float*)d_in[6];
    const float* bv = (const float*)d_in[7];
    const float* wo = (const float*)d_in[8];
    const float* bo = (const float*)d_in[9];
    float* out = (float*)d_out;

    float *Qp, *Kp, *Vp, *Zp;
    __nv_bfloat16 *Xhi, *Xlo, *Zhi, *Zlo;
    cudaGetSymbolAddress((void**)&Qp, g_Q);
    cudaGetSymbolAddress((void**)&Kp, g_K);
    cudaGetSymbolAddress((void**)&Vp, g_V);
    cudaGetSymbolAddress((void**)&Zp, g_Z);
    cudaGetSymbolAddress((void**)&Xhi, g_Xhi);
    cudaGetSymbolAddress((void**)&Xlo, g_Xlo);
    cudaGetSymbolAddress((void**)&Zhi, g_Zhi);
    cudaGetSymbolAddress((void**)&Zlo, g_Zlo);

    const int attn_smem = (4 * 64 * PAD + 64 * 8 + 3 * 64) * (int)sizeof(float);
    cudaFuncSetAttribute(attn_kernel, cudaFuncAttributeMaxDynamicSharedMemorySize, attn_smem);
    cudaFuncSetAttribute(qkv_mma_kernel, cudaFuncAttributeMaxDynamicSharedMemorySize, GEMM_SMEM);
    cudaFuncSetAttribute(out_mma_kernel, cudaFuncAttributeMaxDynamicSharedMemorySize, GEMM_SMEM);

    // split X into bf16 hi/lo; split+transpose all 4 weight matrices
    cvt_split_kernel<<<(MROWS * EMB / 4) / 256, 256>>>(X, Xhi, Xlo);
    cvt_splitT_kernel<<<dim3(EMB / 32, EMB / 32, 4), 256>>>(wq, wk, wv, wo);

    // QKV projections via HMMA bf16x3 (z selects which)
    qkv_mma_kernel<<<dim3(EMB / 128, MROWS / 128, 3), 256, GEMM_SMEM>>>(bq, bk, bv);

    // causal flash attention (fp32) -> g_Z in [B,H,S,Dh]
    attn_kernel<<<dim3(SEQ / 64, BATCH * HEADS), 128, attn_smem>>>(Qp, Kp, Vp);

    // split Z and run output projection
    cvt_split_kernel<<<(MROWS * EMB / 4) / 256, 256>>>(Zp, Zhi, Zlo);
    out_mma_kernel<<<dim3(EMB / 128, MROWS / 128, 1), 256, GEMM_SMEM>>>(bo, out);

    (void)in_sizes; (void)n_in; (void)out_size;
}

// round 6
// speedup vs baseline: 2.4179x; 1.6105x over previous
#include <cuda_runtime.h>
#include <cuda_bf16.h>
#include <cstdint>

// Problem constants
#define BATCH   4
#define SEQ     1024
#define EMB     1024
#define HEADS   16
#define HDIM    64
#define MROWS   (BATCH * SEQ)      // 4096

// ---------------- scratch (16B-aligned for cp.async) ----------------
__device__ __align__(256) __nv_bfloat16 g_Xhi[MROWS * EMB];
__device__ __align__(256) __nv_bfloat16 g_Xlo[MROWS * EMB];
__device__ __align__(256) __nv_bfloat16 g_Qhi[MROWS * EMB];
__device__ __align__(256) __nv_bfloat16 g_Qlo[MROWS * EMB];
__device__ __align__(256) __nv_bfloat16 g_Khi[MROWS * EMB];
__device__ __align__(256) __nv_bfloat16 g_Klo[MROWS * EMB];
__device__ __align__(256) __nv_bfloat16 g_Vhi[MROWS * EMB];
__device__ __align__(256) __nv_bfloat16 g_Vlo[MROWS * EMB];
__device__ __align__(256) __nv_bfloat16 g_Zhi[MROWS * EMB];
__device__ __align__(256) __nv_bfloat16 g_Zlo[MROWS * EMB];
// 4 weight matrices, transposed to [N,K] K-major: order wq, wk, wv, wo
__device__ __align__(256) __nv_bfloat16 g_Whi[4 * EMB * EMB];
__device__ __align__(256) __nv_bfloat16 g_Wlo[4 * EMB * EMB];

// ================= PTX helpers (sm_80+ subset only) =============
__device__ __forceinline__ uint32_t smem_u32(const void* p) {
    uint32_t a;
    asm("{ .reg .u64 t; cvta.to.shared.u64 t, %1; cvt.u32.u64 %0, t; }" : "=r"(a) : "l"(p));
    return a;
}

__device__ __forceinline__ void cp_async16(uint32_t saddr, const void* gaddr) {
    asm volatile("cp.async.cg.shared.global [%0], [%1], 16;" :: "r"(saddr), "l"(gaddr));
}
#define CP_COMMIT()  asm volatile("cp.async.commit_group;" ::: "memory")
template <int N>
__device__ __forceinline__ void cp_wait() {
    asm volatile("cp.async.wait_group %0;" :: "n"(N) : "memory");
}

__device__ __forceinline__ void ldmatrix_x4(uint32_t (&r)[4], uint32_t addr) {
    asm volatile("ldmatrix.sync.aligned.m8n8.x4.shared.b16 {%0,%1,%2,%3}, [%4];"
                 : "=r"(r[0]), "=r"(r[1]), "=r"(r[2]), "=r"(r[3]) : "r"(addr));
}
__device__ __forceinline__ void ldmatrix_x4_trans(uint32_t (&r)[4], uint32_t addr) {
    asm volatile("ldmatrix.sync.aligned.m8n8.x4.trans.shared.b16 {%0,%1,%2,%3}, [%4];"
                 : "=r"(r[0]), "=r"(r[1]), "=r"(r[2]), "=r"(r[3]) : "r"(addr));
}

__device__ __forceinline__ void mma_16816(float (&d)[4], const uint32_t (&a)[4],
                                          uint32_t b0, uint32_t b1) {
    asm volatile(
        "mma.sync.aligned.m16n8k16.row.col.f32.bf16.bf16.f32 "
        "{%0,%1,%2,%3}, {%4,%5,%6,%7}, {%8,%9}, {%0,%1,%2,%3};"
        : "+f"(d[0]), "+f"(d[1]), "+f"(d[2]), "+f"(d[3])
        : "r"(a[0]), "r"(a[1]), "r"(a[2]), "r"(a[3]), "r"(b0), "r"(b1));
}

// fp32 pair -> packed bf16x2 hi + lo
__device__ __forceinline__ void split2(float x, float y, uint32_t& hi, uint32_t& lo) {
    __nv_bfloat16 hx = __float2bfloat16(x);
    __nv_bfloat16 hy = __float2bfloat16(y);
    __nv_bfloat16 lx = __float2bfloat16(x - __bfloat162float(hx));
    __nv_bfloat16 ly = __float2bfloat16(y - __bfloat162float(hy));
    __nv_bfloat162 hp(hx, hy), lp(lx, ly);
    hi = *(uint32_t*)&hp;
    lo = *(uint32_t*)&lp;
}

// ================= conversion kernels =================
__global__ __launch_bounds__(256) void cvt_split_kernel(
    const float* __restrict__ src, __nv_bfloat16* __restrict__ hi,
    __nv_bfloat16* __restrict__ lo)
{
    int i = blockIdx.x * blockDim.x + threadIdx.x;     // one float4 each
    float4 v = ((const float4*)src)[i];
    uint32_t h0, l0, h1, l1;
    split2(v.x, v.y, h0, l0);
    split2(v.z, v.w, h1, l1);
    ((uint2*)hi)[i] = make_uint2(h0, h1);
    ((uint2*)lo)[i] = make_uint2(l0, l1);
}

// W [K,N] fp32 -> WT [N,K] hi/lo bf16 (transpose+split). z selects matrix.
__global__ __launch_bounds__(256) void cvt_splitT_kernel(
    const float* __restrict__ w0, const float* __restrict__ w1,
    const float* __restrict__ w2, const float* __restrict__ w3)
{
    __shared__ float t[32][33];
    const int z = blockIdx.z;
    const float* W = (z == 0) ? w0 : (z == 1) ? w1 : (z == 2) ? w2 : w3;
    __nv_bfloat16* hiT = g_Whi + (size_t)z * EMB * EMB;
    __nv_bfloat16* loT = g_Wlo + (size_t)z * EMB * EMB;
    const int bx = blockIdx.x * 32;   // N base
    const int by = blockIdx.y * 32;   // K base
    const int tx = threadIdx.x & 31;
    const int ty = threadIdx.x >> 5;  // 0..7
    for (int i = ty; i < 32; i += 8)
        t[i][tx] = W[(size_t)(by + i) * EMB + bx + tx];
    __syncthreads();
    for (int i = ty; i < 32; i += 8) {
        float v = t[tx][i];                               // W[by+tx][bx+i]
        __nv_bfloat16 h = __float2bfloat16(v);
        __nv_bfloat16 l = __float2bfloat16(v - __bfloat162float(h));
        hiT[(size_t)(bx + i) * EMB + by + tx] = h;        // WT[n][k]
        loT[(size_t)(bx + i) * EMB + by + tx] = l;
    }
}

// ================= HMMA bf16x3 GEMM =================
// CTA 128x128, BK=32, double-buffered cp.async, 8 warps of 64x32.
#define BK          32
#define NCHUNK      (EMB / BK)              // 32
#define SA          40                       // smem row stride (elems)
#define SPLIT_BYTES (128 * SA * 2)          // 10240
#define STAGE_BYTES (4 * SPLIT_BYTES)       // 40960
#define GEMM_SMEM   (2 * STAGE_BYTES)       // 81920

__device__ __forceinline__ void load_stage_async(
    uint32_t smb, const __nv_bfloat16* __restrict__ Ahi, const __nv_bfloat16* __restrict__ Alo,
    const __nv_bfloat16* __restrict__ Bhi, const __nv_bfloat16* __restrict__ Blo,
    int mbase, int nbase, int k0, int buf, int tid)
{
    const __nv_bfloat16* gsrc[4] = {
        Ahi + (size_t)mbase * EMB + k0, Alo + (size_t)mbase * EMB + k0,
        Bhi + (size_t)nbase * EMB + k0, Blo + (size_t)nbase * EMB + k0 };
    const uint32_t sbase = smb + buf * STAGE_BYTES;
#pragma unroll
    for (int m = 0; m < 4; ++m) {
#pragma unroll
        for (int i = 0; i < 2; ++i) {
            int idx = tid + i * 256;
            int r = idx >> 2, seg = idx & 3;
            uint32_t sa = sbase + m * SPLIT_BYTES + (r * SA + seg * 8) * 2;
            cp_async16(sa, gsrc[m] + (size_t)r * EMB + seg * 8);
        }
    }
}

// SPLIT=true: write bf16 hi/lo to Chi/Clo. SPLIT=false: write f32 to Cf.
template <bool SPLIT>
__device__ __forceinline__ void gemm_body_bf16(
    const __nv_bfloat16* __restrict__ Ahi, const __nv_bfloat16* __restrict__ Alo,
    const __nv_bfloat16* __restrict__ Bhi, const __nv_bfloat16* __restrict__ Blo,
    const float* __restrict__ bias, float* __restrict__ Cf,
    __nv_bfloat16* __restrict__ Chi, __nv_bfloat16* __restrict__ Clo)
{
    extern __shared__ char sm[];
    const uint32_t smb = smem_u32(sm);
    const int tid  = threadIdx.x;          // 256 threads
    const int wid  = tid >> 5;
    const int lane = tid & 31;
    const int mbase = blockIdx.y * 128;
    const int nbase = blockIdx.x * 128;

    const int wm = (wid & 1) * 64;
    const int wn = (wid >> 1) * 32;

    float acc[4][4][4];
#pragma unroll
    for (int mi = 0; mi < 4; ++mi)
#pragma unroll
        for (int ni = 0; ni < 4; ++ni)
#pragma unroll
            for (int e = 0; e < 4; ++e) acc[mi][ni][e] = 0.f;

    const int a_row = (lane & 15);
    const int a_koff = (lane >> 4) * 8;
    const int b_row = (lane & 7) + ((lane >> 4) * 8);
    const int b_koff = ((lane >> 3) & 1) * 8;

    load_stage_async(smb, Ahi, Alo, Bhi, Blo, mbase, nbase, 0, 0, tid);
    CP_COMMIT();

    for (int ck = 0; ck < NCHUNK; ++ck) {
        const int buf = ck & 1;
        if (ck + 1 < NCHUNK) {
            load_stage_async(smb, Ahi, Alo, Bhi, Blo, mbase, nbase, (ck + 1) * BK, buf ^ 1, tid);
            CP_COMMIT();
            cp_wait<1>();
        } else {
            cp_wait<0>();
        }
        __syncthreads();

        const uint32_t sAhi = smb + buf * STAGE_BYTES;
        const uint32_t sAlo = sAhi + SPLIT_BYTES;
        const uint32_t sBhi = sAhi + 2 * SPLIT_BYTES;
        const uint32_t sBlo = sAhi + 3 * SPLIT_BYTES;

#pragma unroll
        for (int ks = 0; ks < 2; ++ks) {
            const int k0 = ks * 16;
            uint32_t ahi[4][4], alo[4][4];
#pragma unroll
            for (int mi = 0; mi < 4; ++mi) {
                uint32_t off = ((wm + mi * 16 + a_row) * SA + k0 + a_koff) * 2;
                ldmatrix_x4(ahi[mi], sAhi + off);
                ldmatrix_x4(alo[mi], sAlo + off);
            }
            uint32_t bhi[2][4], blo[2][4];
#pragma unroll
            for (int bi = 0; bi < 2; ++bi) {
                uint32_t off = ((wn + bi * 16 + b_row) * SA + k0 + b_koff) * 2;
                ldmatrix_x4(bhi[bi], sBhi + off);
                ldmatrix_x4(blo[bi], sBlo + off);
            }
#pragma unroll
            for (int mi = 0; mi < 4; ++mi) {
#pragma unroll
                for (int ni = 0; ni < 4; ++ni) {
                    const int g = ni >> 1, h = (ni & 1) * 2;
                    mma_16816(acc[mi][ni], ahi[mi], bhi[g][h], bhi[g][h + 1]);
                    mma_16816(acc[mi][ni], ahi[mi], blo[g][h], blo[g][h + 1]);
                    mma_16816(acc[mi][ni], alo[mi], bhi[g][h], bhi[g][h + 1]);
                }
            }
        }
        __syncthreads();
    }

    const int fr = lane >> 2;
    const int fc = (lane & 3) * 2;
#pragma unroll
    for (int mi = 0; mi < 4; ++mi) {
#pragma unroll
        for (int ni = 0; ni < 4; ++ni) {
            const int col = nbase + wn + ni * 8 + fc;
            const float b0 = bias[col], b1 = bias[col + 1];
            const int row0 = mbase + wm + mi * 16 + fr;
            const float v0 = acc[mi][ni][0] + b0;
            const float v1 = acc[mi][ni][1] + b1;
            const float v2 = acc[mi][ni][2] + b0;
            const float v3 = acc[mi][ni][3] + b1;
            if (SPLIT) {
                uint32_t h01, l01, h23, l23;
                split2(v0, v1, h01, l01);
                split2(v2, v3, h23, l23);
                *(uint32_t*)(Chi + (size_t)row0 * EMB + col)       = h01;
                *(uint32_t*)(Clo + (size_t)row0 * EMB + col)       = l01;
                *(uint32_t*)(Chi + (size_t)(row0 + 8) * EMB + col) = h23;
                *(uint32_t*)(Clo + (size_t)(row0 + 8) * EMB + col) = l23;
            } else {
                float* p0 = Cf + (size_t)row0 * EMB + col;
                float* p1 = Cf + (size_t)(row0 + 8) * EMB + col;
                p0[0] = v0; p0[1] = v1;
                p1[0] = v2; p1[1] = v3;
            }
        }
    }
}

__global__ __launch_bounds__(256, 1)
void qkv_mma_kernel(const float* __restrict__ bq, const float* __restrict__ bk,
                    const float* __restrict__ bv)
{
    const int z = blockIdx.z;
    const __nv_bfloat16* Bh = g_Whi + (size_t)z * EMB * EMB;
    const __nv_bfloat16* Bl = g_Wlo + (size_t)z * EMB * EMB;
    const float* bias = (z == 0) ? bq : (z == 1) ? bk : bv;
    __nv_bfloat16* Chi = (z == 0) ? g_Qhi : (z == 1) ? g_Khi : g_Vhi;
    __nv_bfloat16* Clo = (z == 0) ? g_Qlo : (z == 1) ? g_Klo : g_Vlo;
    gemm_body_bf16<true>(g_Xhi, g_Xlo, Bh, Bl, bias, nullptr, Chi, Clo);
}

__global__ __launch_bounds__(256, 1)
void out_mma_kernel(const float* __restrict__ bo, float* __restrict__ out)
{
    gemm_body_bf16<false>(g_Zhi, g_Zlo, g_Whi + (size_t)3 * EMB * EMB,
                          g_Wlo + (size_t)3 * EMB * EMB, bo, out, nullptr, nullptr);
}

// ================= Flash attention via HMMA bf16x3 =================
// Br=128, Bc=64. grid (SEQ/128, B*H), 256 threads = 8 warps x 16 rows.
#define ASTR 72   // smem row stride (elems); 144B rows, ldmatrix conflict-free
#define ATTN_SMEM ((2 * 128 + 4 * 64) * ASTR * 2)   // 73728 bytes

__global__ __launch_bounds__(256) void attn_mma_kernel()
{
    extern __shared__ char smraw[];
    const uint32_t uQh = smem_u32(smraw);
    const uint32_t uQl = uQh + 128 * ASTR * 2;
    const uint32_t uKh = uQl + 128 * ASTR * 2;
    const uint32_t uKl = uKh + 64 * ASTR * 2;
    const uint32_t uVh = uKl + 64 * ASTR * 2;
    const uint32_t uVl = uVh + 64 * ASTR * 2;

    const int tid = threadIdx.x, wid = tid >> 5, lane = tid & 31;
    const int qb = blockIdx.x;           // 0..7
    const int bh = blockIdx.y;           // 0..63
    const int b  = bh >> 4, h = bh & 15;
    const size_t gbase = (size_t)b * SEQ * EMB + (size_t)h * HDIM;

    // ---- load Q tile (128 x 64) hi/lo: 1024 x 16B chunks per array ----
#pragma unroll
    for (int i = 0; i < 4; ++i) {
        int idx = tid + i * 256;
        int r = idx >> 3, seg = idx & 7;
        const size_t g = gbase + (size_t)(qb * 128 + r) * EMB + seg * 8;
        const uint32_t so = (r * ASTR + seg * 8) * 2;
        cp_async16(uQh + so, g_Qhi + g);
        cp_async16(uQl + so, g_Qlo + g);
    }
    CP_COMMIT();

    float o[8][4];
#pragma unroll
    for (int nt = 0; nt < 8; ++nt)
#pragma unroll
        for (int e = 0; e < 4; ++e) o[nt][e] = 0.f;
    float m0 = -1e30f, m1 = -1e30f, l0 = 0.f, l1 = 0.f;

    const int r0g = qb * 128 + wid * 16 + (lane >> 2);   // global row of acc elems 0/1

    // ldmatrix addressing
    const int a_row = lane & 15;
    const int a_koff = (lane >> 4) * 8;
    const int b_row = (lane & 7) + ((lane >> 4) * 8);
    const int b_koff = ((lane >> 3) & 1) * 8;

    const int jmax = 2 * qb + 1;
    for (int jb = 0; jb <= jmax; ++jb) {
        // ---- load K/V tiles (64 x 64) hi/lo: 512 x 16B chunks per array ----
#pragma unroll
        for (int i = 0; i < 2; ++i) {
            int idx = tid + i * 256;
            int r = idx >> 3, seg = idx & 7;
            const size_t g = gbase + (size_t)(jb * 64 + r) * EMB + seg * 8;
            const uint32_t so = (r * ASTR + seg * 8) * 2;
            cp_async16(uKh + so, g_Khi + g);
            cp_async16(uKl + so, g_Klo + g);
            cp_async16(uVh + so, g_Vhi + g);
            cp_async16(uVl + so, g_Vlo + g);
        }
        CP_COMMIT();
        cp_wait<0>();
        __syncthreads();

        // ---- S = Q @ K^T (3-term split) ----
        float s[8][4];
#pragma unroll
        for (int nt = 0; nt < 8; ++nt)
#pragma unroll
            for (int e = 0; e < 4; ++e) s[nt][e] = 0.f;

#pragma unroll
        for (int ks = 0; ks < 4; ++ks) {
            uint32_t qh[4], ql[4];
            {
                uint32_t off = ((wid * 16 + a_row) * ASTR + ks * 16 + a_koff) * 2;
                ldmatrix_x4(qh, uQh + off);
                ldmatrix_x4(ql, uQl + off);
            }
            uint32_t kh[4][4], kl[4][4];
#pragma unroll
            for (int g = 0; g < 4; ++g) {
                uint32_t off = ((g * 16 + b_row) * ASTR + ks * 16 + b_koff) * 2;
                ldmatrix_x4(kh[g], uKh + off);
                ldmatrix_x4(kl[g], uKl + off);
            }
#pragma unroll
            for (int g = 0; g < 4; ++g) {
#pragma unroll
                for (int hh = 0; hh < 2; ++hh) {
                    const int nt = 2 * g + hh;
                    mma_16816(s[nt], qh, kh[g][hh * 2], kh[g][hh * 2 + 1]);
                    mma_16816(s[nt], qh, kl[g][hh * 2], kl[g][hh * 2 + 1]);
                    mma_16816(s[nt], ql, kh[g][hh * 2], kh[g][hh * 2 + 1]);
                }
            }
        }

        // ---- scale (0.5 = 1/16^0.25) + causal mask + online softmax ----
        const bool needmask = (jb >= 2 * qb);
        float mx0 = -1e30f, mx1 = -1e30f;
#pragma unroll
        for (int nt = 0; nt < 8; ++nt) {
            if (needmask) {
                const int c = jb * 64 + nt * 8 + (lane & 3) * 2;
                s[nt][0] = (c     <= r0g)     ? s[nt][0] * 0.5f : -1e30f;
                s[nt][1] = (c + 1 <= r0g)     ? s[nt][1] * 0.5f : -1e30f;
                s[nt][2] = (c     <= r0g + 8) ? s[nt][2] * 0.5f : -1e30f;
                s[nt][3] = (c + 1 <= r0g + 8) ? s[nt][3] * 0.5f : -1e30f;
            } else {
                s[nt][0] *= 0.5f; s[nt][1] *= 0.5f;
                s[nt][2] *= 0.5f; s[nt][3] *= 0.5f;
            }
            mx0 = fmaxf(mx0, fmaxf(s[nt][0], s[nt][1]));
            mx1 = fmaxf(mx1, fmaxf(s[nt][2], s[nt][3]));
        }
        mx0 = fmaxf(mx0, __shfl_xor_sync(0xffffffffu, mx0, 1));
        mx0 = fmaxf(mx0, __shfl_xor_sync(0xffffffffu, mx0, 2));
        mx1 = fmaxf(mx1, __shfl_xor_sync(0xffffffffu, mx1, 1));
        mx1 = fmaxf(mx1, __shfl_xor_sync(0xffffffffu, mx1, 2));

        const float nm0 = fmaxf(m0, mx0), nm1 = fmaxf(m1, mx1);
        const float al0 = __expf(m0 - nm0), al1 = __expf(m1 - nm1);
        m0 = nm0; m1 = nm1;

        float rs0 = 0.f, rs1 = 0.f;
#pragma unroll
        for (int nt = 0; nt < 8; ++nt) {
            s[nt][0] = __expf(s[nt][0] - m0);
            s[nt][1] = __expf(s[nt][1] - m0);
            s[nt][2] = __expf(s[nt][2] - m1);
            s[nt][3] = __expf(s[nt][3] - m1);
            rs0 += s[nt][0] + s[nt][1];
            rs1 += s[nt][2] + s[nt][3];
        }
        rs0 += __shfl_xor_sync(0xffffffffu, rs0, 1);
        rs0 += __shfl_xor_sync(0xffffffffu, rs0, 2);
        rs1 += __shfl_xor_sync(0xffffffffu, rs1, 1);
        rs1 += __shfl_xor_sync(0xffffffffu, rs1, 2);
        l0 = l0 * al0 + rs0;
        l1 = l1 * al1 + rs1;

#pragma unroll
        for (int nt = 0; nt < 8; ++nt) {
            o[nt][0] *= al0; o[nt][1] *= al0;
            o[nt][2] *= al1; o[nt][3] *= al1;
        }

        // ---- O += P @ V (3-term split; P from S fragments, V via trans ldmatrix) ----
#pragma unroll
        for (int ks = 0; ks < 4; ++ks) {     // k = t dimension, 16 per step
            uint32_t ph[4], pl[4];
            split2(s[2 * ks][0],     s[2 * ks][1],     ph[0], pl[0]);
            split2(s[2 * ks][2],     s[2 * ks][3],     ph[1], pl[1]);
            split2(s[2 * ks + 1][0], s[2 * ks + 1][1], ph[2], pl[2]);
            split2(s[2 * ks + 1][2], s[2 * ks + 1][3], ph[3], pl[3]);

            uint32_t vh[4][4], vl[4][4];
#pragma unroll
            for (int dg = 0; dg < 4; ++dg) {
                uint32_t off = (((lane & 15) + ks * 16) * ASTR + dg * 16 + (lane >> 4) * 8) * 2;
                ldmatrix_x4_trans(vh[dg], uVh + off);
                ldmatrix_x4_trans(vl[dg], uVl + off);
            }
#pragma unroll
            for (int dg = 0; dg < 4; ++dg) {
#pragma unroll
                for (int hh = 0; hh < 2; ++hh) {
                    const int nt = 2 * dg + hh;
                    mma_16816(o[nt], ph, vh[dg][hh * 2], vh[dg][hh * 2 + 1]);
                    mma_16816(o[nt], ph, vl[dg][hh * 2], vl[dg][hh * 2 + 1]);
                    mma_16816(o[nt], pl, vh[dg][hh * 2], vh[dg][hh * 2 + 1]);
                }
            }
        }
        __syncthreads();   // before next iteration overwrites K/V
    }

    // ---- normalize + write Zhi/Zlo ([B,H,S,Dh] flat) ----
    const float inv0 = 1.f / l0, inv1 = 1.f / l1;
    const int r0 = wid * 16 + (lane >> 2);
    const size_t zr0 = ((size_t)bh * SEQ + (size_t)qb * 128 + r0) * HDIM;
    const size_t zr1 = zr0 + 8 * HDIM;
#pragma unroll
    for (int nt = 0; nt < 8; ++nt) {
        const int c = nt * 8 + (lane & 3) * 2;
        uint32_t h01, l01, h23, l23;
        split2(o[nt][0] * inv0, o[nt][1] * inv0, h01, l01);
        split2(o[nt][2] * inv1, o[nt][3] * inv1, h23, l23);
        *(uint32_t*)(g_Zhi + zr0 + c) = h01;
        *(uint32_t*)(g_Zlo + zr0 + c) = l01;
        *(uint32_t*)(g_Zhi + zr1 + c) = h23;
        *(uint32_t*)(g_Zlo + zr1 + c) = l23;
    }
}

// ---------------- launch ----------------
extern "C" void kernel_launch(void* const* d_in, const int* in_sizes, int n_in,
                              void* d_out, int out_size)
{
    const float* X  = (const float*)d_in[0];
    const float* wq = (const float*)d_in[2];
    const float* bq = (const float*)d_in[3];
    const float* wk = (const float*)d_in[4];
    const float* bk = (const float*)d_in[5];
    const float* wv = (const float*)d_in[6];
    const float* bv = (const float*)d_in[7];
    const float* wo = (const float*)d_in[8];
    const float* bo = (const float*)d_in[9];
    float* out = (float*)d_out;

    __nv_bfloat16 *Xhi, *Xlo;
    cudaGetSymbolAddress((void**)&Xhi, g_Xhi);
    cudaGetSymbolAddress((void**)&Xlo, g_Xlo);

    cudaFuncSetAttribute(attn_mma_kernel, cudaFuncAttributeMaxDynamicSharedMemorySize, ATTN_SMEM);
    cudaFuncSetAttribute(qkv_mma_kernel, cudaFuncAttributeMaxDynamicSharedMemorySize, GEMM_SMEM);
    cudaFuncSetAttribute(out_mma_kernel, cudaFuncAttributeMaxDynamicSharedMemorySize, GEMM_SMEM);

    // split X into bf16 hi/lo; split+transpose all 4 weight matrices
    cvt_split_kernel<<<(MROWS * EMB / 4) / 256, 256>>>(X, Xhi, Xlo);
    cvt_splitT_kernel<<<dim3(EMB / 32, EMB / 32, 4), 256>>>(wq, wk, wv, wo);

    // QKV projections via HMMA bf16x3, emitting bf16 hi/lo directly
    qkv_mma_kernel<<<dim3(EMB / 128, MROWS / 128, 3), 256, GEMM_SMEM>>>(bq, bk, bv);

    // causal flash attention via HMMA bf16x3 -> g_Zhi/g_Zlo
    attn_mma_kernel<<<dim3(SEQ / 128, BATCH * HEADS), 256, ATTN_SMEM>>>();

    // output projection
    out_mma_kernel<<<dim3(EMB / 128, MROWS / 128, 1), 256, GEMM_SMEM>>>(bo, out);

    (void)in_sizes; (void)n_in; (void)out_size;
}

// round 7
// speedup vs baseline: 2.7237x; 1.1265x over previous
#include <cuda_runtime.h>
#include <cuda_bf16.h>
#include <cstdint>

// Problem constants
#define BATCH   4
#define SEQ     1024
#define EMB     1024
#define HEADS   16
#define HDIM    64
#define MROWS   (BATCH * SEQ)      // 4096

// ---------------- scratch (16B-aligned for cp.async) ----------------
__device__ __align__(256) __nv_bfloat16 g_Xhi[MROWS * EMB];
__device__ __align__(256) __nv_bfloat16 g_Xlo[MROWS * EMB];
// Q/K/V in per-head layout [B, H, S, HDIM]
__device__ __align__(256) __nv_bfloat16 g_Qhi[MROWS * EMB];
__device__ __align__(256) __nv_bfloat16 g_Qlo[MROWS * EMB];
__device__ __align__(256) __nv_bfloat16 g_Khi[MROWS * EMB];
__device__ __align__(256) __nv_bfloat16 g_Klo[MROWS * EMB];
__device__ __align__(256) __nv_bfloat16 g_Vhi[MROWS * EMB];
__device__ __align__(256) __nv_bfloat16 g_Vlo[MROWS * EMB];
__device__ __align__(256) __nv_bfloat16 g_Zhi[MROWS * EMB];
__device__ __align__(256) __nv_bfloat16 g_Zlo[MROWS * EMB];
// 4 weight matrices, transposed to [N,K] K-major: order wq, wk, wv, wo
__device__ __align__(256) __nv_bfloat16 g_Whi[4 * EMB * EMB];
__device__ __align__(256) __nv_bfloat16 g_Wlo[4 * EMB * EMB];

// ================= PTX helpers (sm_80+ subset only) =============
__device__ __forceinline__ uint32_t smem_u32(const void* p) {
    uint32_t a;
    asm("{ .reg .u64 t; cvta.to.shared.u64 t, %1; cvt.u32.u64 %0, t; }" : "=r"(a) : "l"(p));
    return a;
}

__device__ __forceinline__ void cp_async16(uint32_t saddr, const void* gaddr) {
    asm volatile("cp.async.cg.shared.global [%0], [%1], 16;" :: "r"(saddr), "l"(gaddr));
}
#define CP_COMMIT()  asm volatile("cp.async.commit_group;" ::: "memory")
template <int N>
__device__ __forceinline__ void cp_wait() {
    asm volatile("cp.async.wait_group %0;" :: "n"(N) : "memory");
}

__device__ __forceinline__ void ldmatrix_x4(uint32_t (&r)[4], uint32_t addr) {
    asm volatile("ldmatrix.sync.aligned.m8n8.x4.shared.b16 {%0,%1,%2,%3}, [%4];"
                 : "=r"(r[0]), "=r"(r[1]), "=r"(r[2]), "=r"(r[3]) : "r"(addr));
}
__device__ __forceinline__ void ldmatrix_x4_trans(uint32_t (&r)[4], uint32_t addr) {
    asm volatile("ldmatrix.sync.aligned.m8n8.x4.trans.shared.b16 {%0,%1,%2,%3}, [%4];"
                 : "=r"(r[0]), "=r"(r[1]), "=r"(r[2]), "=r"(r[3]) : "r"(addr));
}

__device__ __forceinline__ void mma_16816(float (&d)[4], const uint32_t (&a)[4],
                                          uint32_t b0, uint32_t b1) {
    asm volatile(
        "mma.sync.aligned.m16n8k16.row.col.f32.bf16.bf16.f32 "
        "{%0,%1,%2,%3}, {%4,%5,%6,%7}, {%8,%9}, {%0,%1,%2,%3};"
        : "+f"(d[0]), "+f"(d[1]), "+f"(d[2]), "+f"(d[3])
        : "r"(a[0]), "r"(a[1]), "r"(a[2]), "r"(a[3]), "r"(b0), "r"(b1));
}

// fp32 pair -> packed bf16x2 hi + lo
__device__ __forceinline__ void split2(float x, float y, uint32_t& hi, uint32_t& lo) {
    __nv_bfloat16 hx = __float2bfloat16(x);
    __nv_bfloat16 hy = __float2bfloat16(y);
    __nv_bfloat16 lx = __float2bfloat16(x - __bfloat162float(hx));
    __nv_bfloat16 ly = __float2bfloat16(y - __bfloat162float(hy));
    __nv_bfloat162 hp(hx, hy), lp(lx, ly);
    hi = *(uint32_t*)&hp;
    lo = *(uint32_t*)&lp;
}

// ================= conversion kernels =================
__global__ __launch_bounds__(256) void cvt_split_kernel(
    const float* __restrict__ src, __nv_bfloat16* __restrict__ hi,
    __nv_bfloat16* __restrict__ lo)
{
    int i = blockIdx.x * blockDim.x + threadIdx.x;     // one float4 each
    float4 v = ((const float4*)src)[i];
    uint32_t h0, l0, h1, l1;
    split2(v.x, v.y, h0, l0);
    split2(v.z, v.w, h1, l1);
    ((uint2*)hi)[i] = make_uint2(h0, h1);
    ((uint2*)lo)[i] = make_uint2(l0, l1);
}

// W [K,N] fp32 -> WT [N,K] hi/lo bf16 (transpose+split). z selects matrix.
__global__ __launch_bounds__(256) void cvt_splitT_kernel(
    const float* __restrict__ w0, const float* __restrict__ w1,
    const float* __restrict__ w2, const float* __restrict__ w3)
{
    __shared__ float t[32][33];
    const int z = blockIdx.z;
    const float* W = (z == 0) ? w0 : (z == 1) ? w1 : (z == 2) ? w2 : w3;
    __nv_bfloat16* hiT = g_Whi + (size_t)z * EMB * EMB;
    __nv_bfloat16* loT = g_Wlo + (size_t)z * EMB * EMB;
    const int bx = blockIdx.x * 32;   // N base
    const int by = blockIdx.y * 32;   // K base
    const int tx = threadIdx.x & 31;
    const int ty = threadIdx.x >> 5;  // 0..7
    for (int i = ty; i < 32; i += 8)
        t[i][tx] = W[(size_t)(by + i) * EMB + bx + tx];
    __syncthreads();
    for (int i = ty; i < 32; i += 8) {
        float v = t[tx][i];                               // W[by+tx][bx+i]
        __nv_bfloat16 h = __float2bfloat16(v);
        __nv_bfloat16 l = __float2bfloat16(v - __bfloat162float(h));
        hiT[(size_t)(bx + i) * EMB + by + tx] = h;        // WT[n][k]
        loT[(size_t)(bx + i) * EMB + by + tx] = l;
    }
}

// ================= HMMA bf16x3 GEMM =================
// CTA 128x128, BK=32, double-buffered cp.async, 8 warps of 64x32.
#define BK          32
#define NCHUNK      (EMB / BK)              // 32
#define SA          40                       // smem row stride (elems)
#define SPLIT_BYTES (128 * SA * 2)          // 10240
#define STAGE_BYTES (4 * SPLIT_BYTES)       // 40960
#define GEMM_SMEM   (2 * STAGE_BYTES)       // 81920

__device__ __forceinline__ void load_stage_async(
    uint32_t smb, const __nv_bfloat16* __restrict__ Ahi, const __nv_bfloat16* __restrict__ Alo,
    const __nv_bfloat16* __restrict__ Bhi, const __nv_bfloat16* __restrict__ Blo,
    int mbase, int nbase, int k0, int buf, int tid)
{
    const __nv_bfloat16* gsrc[4] = {
        Ahi + (size_t)mbase * EMB + k0, Alo + (size_t)mbase * EMB + k0,
        Bhi + (size_t)nbase * EMB + k0, Blo + (size_t)nbase * EMB + k0 };
    const uint32_t sbase = smb + buf * STAGE_BYTES;
#pragma unroll
    for (int m = 0; m < 4; ++m) {
#pragma unroll
        for (int i = 0; i < 2; ++i) {
            int idx = tid + i * 256;
            int r = idx >> 2, seg = idx & 3;
            uint32_t sa = sbase + m * SPLIT_BYTES + (r * SA + seg * 8) * 2;
            cp_async16(sa, gsrc[m] + (size_t)r * EMB + seg * 8);
        }
    }
}

// SPLIT=true: write bf16 hi/lo to Chi/Clo in PER-HEAD layout [B,H,S,HDIM].
// SPLIT=false: write f32 to Cf row-major [MROWS, EMB].
template <bool SPLIT>
__device__ __forceinline__ void gemm_body_bf16(
    const __nv_bfloat16* __restrict__ Ahi, const __nv_bfloat16* __restrict__ Alo,
    const __nv_bfloat16* __restrict__ Bhi, const __nv_bfloat16* __restrict__ Blo,
    const float* __restrict__ bias, float* __restrict__ Cf,
    __nv_bfloat16* __restrict__ Chi, __nv_bfloat16* __restrict__ Clo)
{
    extern __shared__ char sm[];
    const uint32_t smb = smem_u32(sm);
    const int tid  = threadIdx.x;          // 256 threads
    const int wid  = tid >> 5;
    const int lane = tid & 31;
    const int mbase = blockIdx.y * 128;
    const int nbase = blockIdx.x * 128;

    const int wm = (wid & 1) * 64;
    const int wn = (wid >> 1) * 32;

    float acc[4][4][4];
#pragma unroll
    for (int mi = 0; mi < 4; ++mi)
#pragma unroll
        for (int ni = 0; ni < 4; ++ni)
#pragma unroll
            for (int e = 0; e < 4; ++e) acc[mi][ni][e] = 0.f;

    const int a_row = (lane & 15);
    const int a_koff = (lane >> 4) * 8;
    const int b_row = (lane & 7) + ((lane >> 4) * 8);
    const int b_koff = ((lane >> 3) & 1) * 8;

    load_stage_async(smb, Ahi, Alo, Bhi, Blo, mbase, nbase, 0, 0, tid);
    CP_COMMIT();

    for (int ck = 0; ck < NCHUNK; ++ck) {
        const int buf = ck & 1;
        cp_wait<0>();
        __syncthreads();                     // data ready + prev compute on buf^1 done
        if (ck + 1 < NCHUNK) {
            load_stage_async(smb, Ahi, Alo, Bhi, Blo, mbase, nbase, (ck + 1) * BK, buf ^ 1, tid);
            CP_COMMIT();                     // overlaps with compute below
        }

        const uint32_t sAhi = smb + buf * STAGE_BYTES;
        const uint32_t sAlo = sAhi + SPLIT_BYTES;
        const uint32_t sBhi = sAhi + 2 * SPLIT_BYTES;
        const uint32_t sBlo = sAhi + 3 * SPLIT_BYTES;

#pragma unroll
        for (int ks = 0; ks < 2; ++ks) {
            const int k0 = ks * 16;
            uint32_t ahi[4][4], alo[4][4];
#pragma unroll
            for (int mi = 0; mi < 4; ++mi) {
                uint32_t off = ((wm + mi * 16 + a_row) * SA + k0 + a_koff) * 2;
                ldmatrix_x4(ahi[mi], sAhi + off);
                ldmatrix_x4(alo[mi], sAlo + off);
            }
            uint32_t bhi[2][4], blo[2][4];
#pragma unroll
            for (int bi = 0; bi < 2; ++bi) {
                uint32_t off = ((wn + bi * 16 + b_row) * SA + k0 + b_koff) * 2;
                ldmatrix_x4(bhi[bi], sBhi + off);
                ldmatrix_x4(blo[bi], sBlo + off);
            }
#pragma unroll
            for (int mi = 0; mi < 4; ++mi) {
#pragma unroll
                for (int ni = 0; ni < 4; ++ni) {
                    const int g = ni >> 1, h = (ni & 1) * 2;
                    mma_16816(acc[mi][ni], ahi[mi], bhi[g][h], bhi[g][h + 1]);
                    mma_16816(acc[mi][ni], ahi[mi], blo[g][h], blo[g][h + 1]);
                    mma_16816(acc[mi][ni], alo[mi], bhi[g][h], bhi[g][h + 1]);
                }
            }
        }
    }

    const int fr = lane >> 2;
    const int fc = (lane & 3) * 2;
#pragma unroll
    for (int mi = 0; mi < 4; ++mi) {
#pragma unroll
        for (int ni = 0; ni < 4; ++ni) {
            const int col = nbase + wn + ni * 8 + fc;
            const float b0 = bias[col], b1 = bias[col + 1];
            const int row0 = mbase + wm + mi * 16 + fr;
            const float v0 = acc[mi][ni][0] + b0;
            const float v1 = acc[mi][ni][1] + b1;
            const float v2 = acc[mi][ni][2] + b0;
            const float v3 = acc[mi][ni][3] + b1;
            if (SPLIT) {
                // per-head layout: row0 = b*1024 + s ; col = h*64 + d
                const int bb = row0 >> 10, ss = row0 & 1023;
                const int hh = col >> 6,  dd = col & 63;
                const size_t dst = (((size_t)bb * HEADS + hh) * SEQ + ss) * HDIM + dd;
                uint32_t h01, l01, h23, l23;
                split2(v0, v1, h01, l01);
                split2(v2, v3, h23, l23);
                *(uint32_t*)(Chi + dst)            = h01;
                *(uint32_t*)(Clo + dst)            = l01;
                *(uint32_t*)(Chi + dst + 8 * HDIM) = h23;   // row0+8: same b,h
                *(uint32_t*)(Clo + dst + 8 * HDIM) = l23;
            } else {
                float* p0 = Cf + (size_t)row0 * EMB + col;
                float* p1 = Cf + (size_t)(row0 + 8) * EMB + col;
                p0[0] = v0; p0[1] = v1;
                p1[0] = v2; p1[1] = v3;
            }
        }
    }
}

__global__ __launch_bounds__(256, 2)
void qkv_mma_kernel(const float* __restrict__ bq, const float* __restrict__ bk,
                    const float* __restrict__ bv)
{
    const int z = blockIdx.z;
    const __nv_bfloat16* Bh = g_Whi + (size_t)z * EMB * EMB;
    const __nv_bfloat16* Bl = g_Wlo + (size_t)z * EMB * EMB;
    const float* bias = (z == 0) ? bq : (z == 1) ? bk : bv;
    __nv_bfloat16* Chi = (z == 0) ? g_Qhi : (z == 1) ? g_Khi : g_Vhi;
    __nv_bfloat16* Clo = (z == 0) ? g_Qlo : (z == 1) ? g_Klo : g_Vlo;
    gemm_body_bf16<true>(g_Xhi, g_Xlo, Bh, Bl, bias, nullptr, Chi, Clo);
}

__global__ __launch_bounds__(256, 2)
void out_mma_kernel(const float* __restrict__ bo, float* __restrict__ out)
{
    gemm_body_bf16<false>(g_Zhi, g_Zlo, g_Whi + (size_t)3 * EMB * EMB,
                          g_Wlo + (size_t)3 * EMB * EMB, bo, out, nullptr, nullptr);
}

// ================= Flash attention via HMMA bf16x3 =================
// Br=128, Bc=64. grid (SEQ/128, B*H), 256 threads = 8 warps x 16 rows.
// Q/K/V in per-head layout [B,H,S,64]; K/V double-buffered in smem.
#define ASTR 72   // smem row stride (elems); 144B rows, ldmatrix conflict-free
#define Q_BYTES    (128 * ASTR * 2)          // 18432 per split
#define KVBUF      (4 * 64 * ASTR * 2)       // 36864: Kh,Kl,Vh,Vl
#define ATTN_SMEM  (2 * Q_BYTES + 2 * KVBUF) // 110592 bytes

__device__ __forceinline__ void attn_load_kv(uint32_t kvbase, size_t gbase, int jb, int tid)
{
#pragma unroll
    for (int i = 0; i < 2; ++i) {
        int idx = tid + i * 256;                 // 512 x 16B chunks per array
        int r = idx >> 3, seg = idx & 7;
        const size_t g = gbase + (size_t)(jb * 64 + r) * HDIM + seg * 8;
        const uint32_t so = (r * ASTR + seg * 8) * 2;
        cp_async16(kvbase + so,                 g_Khi + g);
        cp_async16(kvbase + 64 * ASTR * 2 + so, g_Klo + g);
        cp_async16(kvbase + 128 * ASTR * 2 + so, g_Vhi + g);
        cp_async16(kvbase + 192 * ASTR * 2 + so, g_Vlo + g);
    }
}

__global__ __launch_bounds__(256, 2) void attn_mma_kernel()
{
    extern __shared__ char smraw[];
    const uint32_t uQh = smem_u32(smraw);
    const uint32_t uQl = uQh + Q_BYTES;
    const uint32_t uKV0 = uQl + Q_BYTES;       // two KV buffers follow

    const int tid = threadIdx.x, wid = tid >> 5, lane = tid & 31;
    const int qb = (int)(gridDim.x - 1 - blockIdx.x);   // long blocks first
    const int bh = blockIdx.y;           // 0..63
    const size_t gbase = (size_t)bh * SEQ * HDIM;

    // ---- load Q tile (128 x 64) hi/lo: contiguous 16 KB per split ----
#pragma unroll
    for (int i = 0; i < 4; ++i) {
        int idx = tid + i * 256;
        int r = idx >> 3, seg = idx & 7;
        const size_t g = gbase + (size_t)(qb * 128 + r) * HDIM + seg * 8;
        const uint32_t so = (r * ASTR + seg * 8) * 2;
        cp_async16(uQh + so, g_Qhi + g);
        cp_async16(uQl + so, g_Qlo + g);
    }
    CP_COMMIT();

    // prologue: K/V tile 0 into buffer 0
    attn_load_kv(uKV0, gbase, 0, tid);
    CP_COMMIT();

    float o[8][4];
#pragma unroll
    for (int nt = 0; nt < 8; ++nt)
#pragma unroll
        for (int e = 0; e < 4; ++e) o[nt][e] = 0.f;
    float m0 = -1e30f, m1 = -1e30f, l0 = 0.f, l1 = 0.f;

    const int r0g = qb * 128 + wid * 16 + (lane >> 2);

    const int a_row = lane & 15;
    const int a_koff = (lane >> 4) * 8;
    const int b_row = (lane & 7) + ((lane >> 4) * 8);
    const int b_koff = ((lane >> 3) & 1) * 8;

    const int jmax = 2 * qb + 1;
    for (int jb = 0; jb <= jmax; ++jb) {
        const uint32_t kvb = uKV0 + (jb & 1) * KVBUF;
        cp_wait<0>();
        __syncthreads();                       // data ready; prev compute on other buf done
        if (jb < jmax) {
            attn_load_kv(uKV0 + ((jb + 1) & 1) * KVBUF, gbase, jb + 1, tid);
            CP_COMMIT();                       // overlaps with compute below
        }
        const uint32_t uKh = kvb;
        const uint32_t uKl = kvb + 64 * ASTR * 2;
        const uint32_t uVh = kvb + 128 * ASTR * 2;
        const uint32_t uVl = kvb + 192 * ASTR * 2;

        // ---- S = Q @ K^T (3-term split) ----
        float s[8][4];
#pragma unroll
        for (int nt = 0; nt < 8; ++nt)
#pragma unroll
            for (int e = 0; e < 4; ++e) s[nt][e] = 0.f;

#pragma unroll
        for (int ks = 0; ks < 4; ++ks) {
            uint32_t qh[4], ql[4];
            {
                uint32_t off = ((wid * 16 + a_row) * ASTR + ks * 16 + a_koff) * 2;
                ldmatrix_x4(qh, uQh + off);
                ldmatrix_x4(ql, uQl + off);
            }
            uint32_t kh[4][4], kl[4][4];
#pragma unroll
            for (int g = 0; g < 4; ++g) {
                uint32_t off = ((g * 16 + b_row) * ASTR + ks * 16 + b_koff) * 2;
                ldmatrix_x4(kh[g], uKh + off);
                ldmatrix_x4(kl[g], uKl + off);
            }
#pragma unroll
            for (int g = 0; g < 4; ++g) {
#pragma unroll
                for (int hh = 0; hh < 2; ++hh) {
                    const int nt = 2 * g + hh;
                    mma_16816(s[nt], qh, kh[g][hh * 2], kh[g][hh * 2 + 1]);
                    mma_16816(s[nt], qh, kl[g][hh * 2], kl[g][hh * 2 + 1]);
                    mma_16816(s[nt], ql, kh[g][hh * 2], kh[g][hh * 2 + 1]);
                }
            }
        }

        // ---- scale (0.5 = 1/16^0.25) + causal mask + online softmax ----
        const bool needmask = (jb >= 2 * qb);
        float mx0 = -1e30f, mx1 = -1e30f;
#pragma unroll
        for (int nt = 0; nt < 8; ++nt) {
            if (needmask) {
                const int c = jb * 64 + nt * 8 + (lane & 3) * 2;
                s[nt][0] = (c     <= r0g)     ? s[nt][0] * 0.5f : -1e30f;
                s[nt][1] = (c + 1 <= r0g)     ? s[nt][1] * 0.5f : -1e30f;
                s[nt][2] = (c     <= r0g + 8) ? s[nt][2] * 0.5f : -1e30f;
                s[nt][3] = (c + 1 <= r0g + 8) ? s[nt][3] * 0.5f : -1e30f;
            } else {
                s[nt][0] *= 0.5f; s[nt][1] *= 0.5f;
                s[nt][2] *= 0.5f; s[nt][3] *= 0.5f;
            }
            mx0 = fmaxf(mx0, fmaxf(s[nt][0], s[nt][1]));
            mx1 = fmaxf(mx1, fmaxf(s[nt][2], s[nt][3]));
        }
        mx0 = fmaxf(mx0, __shfl_xor_sync(0xffffffffu, mx0, 1));
        mx0 = fmaxf(mx0, __shfl_xor_sync(0xffffffffu, mx0, 2));
        mx1 = fmaxf(mx1, __shfl_xor_sync(0xffffffffu, mx1, 1));
        mx1 = fmaxf(mx1, __shfl_xor_sync(0xffffffffu, mx1, 2));

        const float nm0 = fmaxf(m0, mx0), nm1 = fmaxf(m1, mx1);
        const float al0 = __expf(m0 - nm0), al1 = __expf(m1 - nm1);
        m0 = nm0; m1 = nm1;

        float rs0 = 0.f, rs1 = 0.f;
#pragma unroll
        for (int nt = 0; nt < 8; ++nt) {
            s[nt][0] = __expf(s[nt][0] - m0);
            s[nt][1] = __expf(s[nt][1] - m0);
            s[nt][2] = __expf(s[nt][2] - m1);
            s[nt][3] = __expf(s[nt][3] - m1);
            rs0 += s[nt][0] + s[nt][1];
            rs1 += s[nt][2] + s[nt][3];
        }
        rs0 += __shfl_xor_sync(0xffffffffu, rs0, 1);
        rs0 += __shfl_xor_sync(0xffffffffu, rs0, 2);
        rs1 += __shfl_xor_sync(0xffffffffu, rs1, 1);
        rs1 += __shfl_xor_sync(0xffffffffu, rs1, 2);
        l0 = l0 * al0 + rs0;
        l1 = l1 * al1 + rs1;

#pragma unroll
        for (int nt = 0; nt < 8; ++nt) {
            o[nt][0] *= al0; o[nt][1] *= al0;
            o[nt][2] *= al1; o[nt][3] *= al1;
        }

        // ---- O += P @ V (3-term split; P from S fragments, V via trans ldmatrix) ----
#pragma unroll
        for (int ks = 0; ks < 4; ++ks) {
            uint32_t ph[4], pl[4];
            split2(s[2 * ks][0],     s[2 * ks][1],     ph[0], pl[0]);
            split2(s[2 * ks][2],     s[2 * ks][3],     ph[1], pl[1]);
            split2(s[2 * ks + 1][0], s[2 * ks + 1][1], ph[2], pl[2]);
            split2(s[2 * ks + 1][2], s[2 * ks + 1][3], ph[3], pl[3]);

            uint32_t vh[4][4], vl[4][4];
#pragma unroll
            for (int dg = 0; dg < 4; ++dg) {
                uint32_t off = (((lane & 15) + ks * 16) * ASTR + dg * 16 + (lane >> 4) * 8) * 2;
                ldmatrix_x4_trans(vh[dg], uVh + off);
                ldmatrix_x4_trans(vl[dg], uVl + off);
            }
#pragma unroll
            for (int dg = 0; dg < 4; ++dg) {
#pragma unroll
                for (int hh = 0; hh < 2; ++hh) {
                    const int nt = 2 * dg + hh;
                    mma_16816(o[nt], ph, vh[dg][hh * 2], vh[dg][hh * 2 + 1]);
                    mma_16816(o[nt], ph, vl[dg][hh * 2], vl[dg][hh * 2 + 1]);
                    mma_16816(o[nt], pl, vh[dg][hh * 2], vh[dg][hh * 2 + 1]);
                }
            }
        }
    }

    // ---- normalize + write Zhi/Zlo ([B,H,S,Dh] flat) ----
    const float inv0 = 1.f / l0, inv1 = 1.f / l1;
    const int r0 = wid * 16 + (lane >> 2);
    const size_t zr0 = ((size_t)bh * SEQ + (size_t)qb * 128 + r0) * HDIM;
    const size_t zr1 = zr0 + 8 * HDIM;
#pragma unroll
    for (int nt = 0; nt < 8; ++nt) {
        const int c = nt * 8 + (lane & 3) * 2;
        uint32_t h01, l01, h23, l23;
        split2(o[nt][0] * inv0, o[nt][1] * inv0, h01, l01);
        split2(o[nt][2] * inv1, o[nt][3] * inv1, h23, l23);
        *(uint32_t*)(g_Zhi + zr0 + c) = h01;
        *(uint32_t*)(g_Zlo + zr0 + c) = l01;
        *(uint32_t*)(g_Zhi + zr1 + c) = h23;
        *(uint32_t*)(g_Zlo + zr1 + c) = l23;
    }
}

// ---------------- launch ----------------
extern "C" void kernel_launch(void* const* d_in, const int* in_sizes, int n_in,
                              void* d_out, int out_size)
{
    const float* X  = (const float*)d_in[0];
    const float* wq = (const float*)d_in[2];
    const float* bq = (const float*)d_in[3];
    const float* wk = (const float*)d_in[4];
    const float* bk = (const float*)d_in[5];
    const float* wv = (const float*)d_in[6];
    const float* bv = (const float*)d_in[7];
    const float* wo = (const float*)d_in[8];
    const float* bo = (const float*)d_in[9];
    float* out = (float*)d_out;

    __nv_bfloat16 *Xhi, *Xlo;
    cudaGetSymbolAddress((void**)&Xhi, g_Xhi);
    cudaGetSymbolAddress((void**)&Xlo, g_Xlo);

    cudaFuncSetAttribute(attn_mma_kernel, cudaFuncAttributeMaxDynamicSharedMemorySize, ATTN_SMEM);
    cudaFuncSetAttribute(qkv_mma_kernel, cudaFuncAttributeMaxDynamicSharedMemorySize, GEMM_SMEM);
    cudaFuncSetAttribute(out_mma_kernel, cudaFuncAttributeMaxDynamicSharedMemorySize, GEMM_SMEM);

    // split X into bf16 hi/lo; split+transpose all 4 weight matrices
    cvt_split_kernel<<<(MROWS * EMB / 4) / 256, 256>>>(X, Xhi, Xlo);
    cvt_splitT_kernel<<<dim3(EMB / 32, EMB / 32, 4), 256>>>(wq, wk, wv, wo);

    // QKV projections via HMMA bf16x3, emitting per-head bf16 hi/lo directly
    qkv_mma_kernel<<<dim3(EMB / 128, MROWS / 128, 3), 256, GEMM_SMEM>>>(bq, bk, bv);

    // causal flash attention via HMMA bf16x3 -> g_Zhi/g_Zlo
    attn_mma_kernel<<<dim3(SEQ / 128, BATCH * HEADS), 256, ATTN_SMEM>>>();

    // output projection
    out_mma_kernel<<<dim3(EMB / 128, MROWS / 128, 1), 256, GEMM_SMEM>>>(bo, out);

    (void)in_sizes; (void)n_in; (void)out_size;
}

// round 8
// speedup vs baseline: 3.1595x; 1.1600x over previous
#include <cuda_runtime.h>
#include <cuda_bf16.h>
#include <cuda_fp16.h>
#include <cstdint>

// Problem constants
#define BATCH   4
#define SEQ     1024
#define EMB     1024
#define HEADS   16
#define HDIM    64
#define MROWS   (BATCH * SEQ)      // 4096

// ---------------- scratch (16B-aligned for cp.async) ----------------
__device__ __align__(256) __nv_bfloat16 g_Xhi[MROWS * EMB];
__device__ __align__(256) __nv_bfloat16 g_Xlo[MROWS * EMB];
// Q/K in per-head layout [B, H, S, HDIM], bf16 hi/lo; V fp16 hi/lo
__device__ __align__(256) __nv_bfloat16 g_Qhi[MROWS * EMB];
__device__ __align__(256) __nv_bfloat16 g_Qlo[MROWS * EMB];
__device__ __align__(256) __nv_bfloat16 g_Khi[MROWS * EMB];
__device__ __align__(256) __nv_bfloat16 g_Klo[MROWS * EMB];
__device__ __align__(256) __half       g_Vhi[MROWS * EMB];
__device__ __align__(256) __half       g_Vlo[MROWS * EMB];
// Z single fp16 ([B,H,S,Dh] flat = [MROWS, EMB] row-major view)
__device__ __align__(256) __half       g_Z[MROWS * EMB];
// wq,wk,wv transposed [N,K] bf16 hi/lo; wo transposed [N,K] fp16 hi/lo
__device__ __align__(256) __nv_bfloat16 g_Whi[3 * EMB * EMB];
__device__ __align__(256) __nv_bfloat16 g_Wlo[3 * EMB * EMB];
__device__ __align__(256) __half       g_WOhi[EMB * EMB];
__device__ __align__(256) __half       g_WOlo[EMB * EMB];

// ================= PTX helpers (sm_80+ subset only) =============
__device__ __forceinline__ uint32_t smem_u32(const void* p) {
    uint32_t a;
    asm("{ .reg .u64 t; cvta.to.shared.u64 t, %1; cvt.u32.u64 %0, t; }" : "=r"(a) : "l"(p));
    return a;
}

__device__ __forceinline__ void cp_async16(uint32_t saddr, const void* gaddr) {
    asm volatile("cp.async.cg.shared.global [%0], [%1], 16;" :: "r"(saddr), "l"(gaddr));
}
#define CP_COMMIT()  asm volatile("cp.async.commit_group;" ::: "memory")
template <int N>
__device__ __forceinline__ void cp_wait() {
    asm volatile("cp.async.wait_group %0;" :: "n"(N) : "memory");
}

__device__ __forceinline__ void ldmatrix_x4(uint32_t (&r)[4], uint32_t addr) {
    asm volatile("ldmatrix.sync.aligned.m8n8.x4.shared.b16 {%0,%1,%2,%3}, [%4];"
                 : "=r"(r[0]), "=r"(r[1]), "=r"(r[2]), "=r"(r[3]) : "r"(addr));
}
__device__ __forceinline__ void ldmatrix_x4_trans(uint32_t (&r)[4], uint32_t addr) {
    asm volatile("ldmatrix.sync.aligned.m8n8.x4.trans.shared.b16 {%0,%1,%2,%3}, [%4];"
                 : "=r"(r[0]), "=r"(r[1]), "=r"(r[2]), "=r"(r[3]) : "r"(addr));
}

__device__ __forceinline__ void mma_16816(float (&d)[4], const uint32_t (&a)[4],
                                          uint32_t b0, uint32_t b1) {
    asm volatile(
        "mma.sync.aligned.m16n8k16.row.col.f32.bf16.bf16.f32 "
        "{%0,%1,%2,%3}, {%4,%5,%6,%7}, {%8,%9}, {%0,%1,%2,%3};"
        : "+f"(d[0]), "+f"(d[1]), "+f"(d[2]), "+f"(d[3])
        : "r"(a[0]), "r"(a[1]), "r"(a[2]), "r"(a[3]), "r"(b0), "r"(b1));
}
__device__ __forceinline__ void mma_16816_f16(float (&d)[4], const uint32_t (&a)[4],
                                              uint32_t b0, uint32_t b1) {
    asm volatile(
        "mma.sync.aligned.m16n8k16.row.col.f32.f16.f16.f32 "
        "{%0,%1,%2,%3}, {%4,%5,%6,%7}, {%8,%9}, {%0,%1,%2,%3};"
        : "+f"(d[0]), "+f"(d[1]), "+f"(d[2]), "+f"(d[3])
        : "r"(a[0]), "r"(a[1]), "r"(a[2]), "r"(a[3]), "r"(b0), "r"(b1));
}

// fp32 pair -> packed bf16x2 hi + lo
__device__ __forceinline__ void split2(float x, float y, uint32_t& hi, uint32_t& lo) {
    __nv_bfloat16 hx = __float2bfloat16(x);
    __nv_bfloat16 hy = __float2bfloat16(y);
    __nv_bfloat16 lx = __float2bfloat16(x - __bfloat162float(hx));
    __nv_bfloat16 ly = __float2bfloat16(y - __bfloat162float(hy));
    __nv_bfloat162 hp(hx, hy), lp(lx, ly);
    hi = *(uint32_t*)&hp;
    lo = *(uint32_t*)&lp;
}
// fp32 pair -> packed fp16x2 hi + lo
__device__ __forceinline__ void split2h(float x, float y, uint32_t& hi, uint32_t& lo) {
    __half hx = __float2half_rn(x);
    __half hy = __float2half_rn(y);
    __half lx = __float2half_rn(x - __half2float(hx));
    __half ly = __float2half_rn(y - __half2float(hy));
    __half2 hp(hx, hy), lp(lx, ly);
    hi = *(uint32_t*)&hp;
    lo = *(uint32_t*)&lp;
}
__device__ __forceinline__ uint32_t packh2(float x, float y) {
    __half2 h = __floats2half2_rn(x, y);
    return *(uint32_t*)&h;
}

// ================= conversion kernels =================
__global__ __launch_bounds__(256) void cvt_split_kernel(
    const float* __restrict__ src, __nv_bfloat16* __restrict__ hi,
    __nv_bfloat16* __restrict__ lo)
{
    int i = blockIdx.x * blockDim.x + threadIdx.x;     // one float4 each
    float4 v = ((const float4*)src)[i];
    uint32_t h0, l0, h1, l1;
    split2(v.x, v.y, h0, l0);
    split2(v.z, v.w, h1, l1);
    ((uint2*)hi)[i] = make_uint2(h0, h1);
    ((uint2*)lo)[i] = make_uint2(l0, l1);
}

// W [K,N] fp32 -> WT [N,K] hi/lo (transpose+split). z<3: bf16; z==3: fp16.
__global__ __launch_bounds__(256) void cvt_splitT_kernel(
    const float* __restrict__ w0, const float* __restrict__ w1,
    const float* __restrict__ w2, const float* __restrict__ w3)
{
    __shared__ float t[32][33];
    const int z = blockIdx.z;
    const float* W = (z == 0) ? w0 : (z == 1) ? w1 : (z == 2) ? w2 : w3;
    const int bx = blockIdx.x * 32;   // N base
    const int by = blockIdx.y * 32;   // K base
    const int tx = threadIdx.x & 31;
    const int ty = threadIdx.x >> 5;  // 0..7
    for (int i = ty; i < 32; i += 8)
        t[i][tx] = W[(size_t)(by + i) * EMB + bx + tx];
    __syncthreads();
    if (z < 3) {
        __nv_bfloat16* hiT = g_Whi + (size_t)z * EMB * EMB;
        __nv_bfloat16* loT = g_Wlo + (size_t)z * EMB * EMB;
        for (int i = ty; i < 32; i += 8) {
            float v = t[tx][i];
            __nv_bfloat16 h = __float2bfloat16(v);
            __nv_bfloat16 l = __float2bfloat16(v - __bfloat162float(h));
            hiT[(size_t)(bx + i) * EMB + by + tx] = h;
            loT[(size_t)(bx + i) * EMB + by + tx] = l;
        }
    } else {
        for (int i = ty; i < 32; i += 8) {
            float v = t[tx][i];
            __half h = __float2half_rn(v);
            __half l = __float2half_rn(v - __half2float(h));
            g_WOhi[(size_t)(bx + i) * EMB + by + tx] = h;
            g_WOlo[(size_t)(bx + i) * EMB + by + tx] = l;
        }
    }
}

// ================= HMMA bf16x3 QKV GEMM =================
#define BK          32
#define NCHUNK      (EMB / BK)              // 32
#define SA          40                       // smem row stride (elems)
#define SPLIT_BYTES (128 * SA * 2)          // 10240
#define STAGE_BYTES (4 * SPLIT_BYTES)       // 40960
#define GEMM_SMEM   (2 * STAGE_BYTES)       // 81920

__device__ __forceinline__ void load_stage_async(
    uint32_t smb, const __nv_bfloat16* __restrict__ Ahi, const __nv_bfloat16* __restrict__ Alo,
    const __nv_bfloat16* __restrict__ Bhi, const __nv_bfloat16* __restrict__ Blo,
    int mbase, int nbase, int k0, int buf, int tid)
{
    const __nv_bfloat16* gsrc[4] = {
        Ahi + (size_t)mbase * EMB + k0, Alo + (size_t)mbase * EMB + k0,
        Bhi + (size_t)nbase * EMB + k0, Blo + (size_t)nbase * EMB + k0 };
    const uint32_t sbase = smb + buf * STAGE_BYTES;
#pragma unroll
    for (int m = 0; m < 4; ++m) {
#pragma unroll
        for (int i = 0; i < 2; ++i) {
            int idx = tid + i * 256;
            int r = idx >> 2, seg = idx & 3;
            uint32_t sa = sbase + m * SPLIT_BYTES + (r * SA + seg * 8) * 2;
            cp_async16(sa, gsrc[m] + (size_t)r * EMB + seg * 8);
        }
    }
}

// mode 0: Q (bf16 split, x0.5); mode 1: K (bf16 split); mode 2: V (fp16 split)
__global__ __launch_bounds__(256, 2)
void qkv_mma_kernel(const float* __restrict__ bq, const float* __restrict__ bk,
                    const float* __restrict__ bv)
{
    extern __shared__ char sm[];
    const uint32_t smb = smem_u32(sm);
    const int tid  = threadIdx.x;
    const int wid  = tid >> 5;
    const int lane = tid & 31;
    const int mbase = blockIdx.y * 128;
    const int nbase = blockIdx.x * 128;
    const int mode = blockIdx.z;

    const __nv_bfloat16* Bh = g_Whi + (size_t)mode * EMB * EMB;
    const __nv_bfloat16* Bl = g_Wlo + (size_t)mode * EMB * EMB;
    const float* bias = (mode == 0) ? bq : (mode == 1) ? bk : bv;

    const int wm = (wid & 1) * 64;
    const int wn = (wid >> 1) * 32;

    float acc[4][4][4];
#pragma unroll
    for (int mi = 0; mi < 4; ++mi)
#pragma unroll
        for (int ni = 0; ni < 4; ++ni)
#pragma unroll
            for (int e = 0; e < 4; ++e) acc[mi][ni][e] = 0.f;

    const int a_row = (lane & 15);
    const int a_koff = (lane >> 4) * 8;
    const int b_row = (lane & 7) + ((lane >> 4) * 8);
    const int b_koff = ((lane >> 3) & 1) * 8;

    load_stage_async(smb, g_Xhi, g_Xlo, Bh, Bl, mbase, nbase, 0, 0, tid);
    CP_COMMIT();

    for (int ck = 0; ck < NCHUNK; ++ck) {
        const int buf = ck & 1;
        cp_wait<0>();
        __syncthreads();
        if (ck + 1 < NCHUNK) {
            load_stage_async(smb, g_Xhi, g_Xlo, Bh, Bl, mbase, nbase, (ck + 1) * BK, buf ^ 1, tid);
            CP_COMMIT();
        }

        const uint32_t sAhi = smb + buf * STAGE_BYTES;
        const uint32_t sAlo = sAhi + SPLIT_BYTES;
        const uint32_t sBhi = sAhi + 2 * SPLIT_BYTES;
        const uint32_t sBlo = sAhi + 3 * SPLIT_BYTES;

#pragma unroll
        for (int ks = 0; ks < 2; ++ks) {
            const int k0 = ks * 16;
            uint32_t ahi[4][4], alo[4][4];
#pragma unroll
            for (int mi = 0; mi < 4; ++mi) {
                uint32_t off = ((wm + mi * 16 + a_row) * SA + k0 + a_koff) * 2;
                ldmatrix_x4(ahi[mi], sAhi + off);
                ldmatrix_x4(alo[mi], sAlo + off);
            }
            uint32_t bhi[2][4], blo[2][4];
#pragma unroll
            for (int bi = 0; bi < 2; ++bi) {
                uint32_t off = ((wn + bi * 16 + b_row) * SA + k0 + b_koff) * 2;
                ldmatrix_x4(bhi[bi], sBhi + off);
                ldmatrix_x4(blo[bi], sBlo + off);
            }
#pragma unroll
            for (int mi = 0; mi < 4; ++mi) {
#pragma unroll
                for (int ni = 0; ni < 4; ++ni) {
                    const int g = ni >> 1, h = (ni & 1) * 2;
                    mma_16816(acc[mi][ni], ahi[mi], bhi[g][h], bhi[g][h + 1]);
                    mma_16816(acc[mi][ni], ahi[mi], blo[g][h], blo[g][h + 1]);
                    mma_16816(acc[mi][ni], alo[mi], bhi[g][h], bhi[g][h + 1]);
                }
            }
        }
    }

    const int fr = lane >> 2;
    const int fc = (lane & 3) * 2;
    const float qscale = (mode == 0) ? 0.5f : 1.0f;   // fold 1/16^0.25 into Q
#pragma unroll
    for (int mi = 0; mi < 4; ++mi) {
#pragma unroll
        for (int ni = 0; ni < 4; ++ni) {
            const int col = nbase + wn + ni * 8 + fc;
            const float b0 = bias[col], b1 = bias[col + 1];
            const int row0 = mbase + wm + mi * 16 + fr;
            const float v0 = (acc[mi][ni][0] + b0) * qscale;
            const float v1 = (acc[mi][ni][1] + b1) * qscale;
            const float v2 = (acc[mi][ni][2] + b0) * qscale;
            const float v3 = (acc[mi][ni][3] + b1) * qscale;
            // per-head layout: row0 = b*1024 + s ; col = h*64 + d
            const int bb = row0 >> 10, ss = row0 & 1023;
            const int hh = col >> 6,  dd = col & 63;
            const size_t dst = (((size_t)bb * HEADS + hh) * SEQ + ss) * HDIM + dd;
            if (mode == 2) {
                uint32_t h01, l01, h23, l23;
                split2h(v0, v1, h01, l01);
                split2h(v2, v3, h23, l23);
                *(uint32_t*)(g_Vhi + dst)            = h01;
                *(uint32_t*)(g_Vlo + dst)            = l01;
                *(uint32_t*)(g_Vhi + dst + 8 * HDIM) = h23;
                *(uint32_t*)(g_Vlo + dst + 8 * HDIM) = l23;
            } else {
                __nv_bfloat16* Chi = (mode == 0) ? g_Qhi : g_Khi;
                __nv_bfloat16* Clo = (mode == 0) ? g_Qlo : g_Klo;
                uint32_t h01, l01, h23, l23;
                split2(v0, v1, h01, l01);
                split2(v2, v3, h23, l23);
                *(uint32_t*)(Chi + dst)            = h01;
                *(uint32_t*)(Clo + dst)            = l01;
                *(uint32_t*)(Chi + dst + 8 * HDIM) = h23;
                *(uint32_t*)(Clo + dst + 8 * HDIM) = l23;
            }
        }
    }
}

// ================= out projection: fp16 2-term (Z single, Wo hi/lo) ========
#define OSTAGE_BYTES (3 * SPLIT_BYTES)       // 30720: A, Bhi, Blo
#define OGEMM_SMEM   (2 * OSTAGE_BYTES)      // 61440

__device__ __forceinline__ void load_stage_out(
    uint32_t smb, int mbase, int nbase, int k0, int buf, int tid)
{
    const __half* gsrc[3] = {
        g_Z    + (size_t)mbase * EMB + k0,
        g_WOhi + (size_t)nbase * EMB + k0,
        g_WOlo + (size_t)nbase * EMB + k0 };
    const uint32_t sbase = smb + buf * OSTAGE_BYTES;
#pragma unroll
    for (int m = 0; m < 3; ++m) {
#pragma unroll
        for (int i = 0; i < 2; ++i) {
            int idx = tid + i * 256;
            int r = idx >> 2, seg = idx & 3;
            uint32_t sa = sbase + m * SPLIT_BYTES + (r * SA + seg * 8) * 2;
            cp_async16(sa, gsrc[m] + (size_t)r * EMB + seg * 8);
        }
    }
}

__global__ __launch_bounds__(256, 2)
void out_mma_kernel(const float* __restrict__ bo, float* __restrict__ out)
{
    extern __shared__ char sm[];
    const uint32_t smb = smem_u32(sm);
    const int tid  = threadIdx.x;
    const int wid  = tid >> 5;
    const int lane = tid & 31;
    const int mbase = blockIdx.y * 128;
    const int nbase = blockIdx.x * 128;

    const int wm = (wid & 1) * 64;
    const int wn = (wid >> 1) * 32;

    float acc[4][4][4];
#pragma unroll
    for (int mi = 0; mi < 4; ++mi)
#pragma unroll
        for (int ni = 0; ni < 4; ++ni)
#pragma unroll
            for (int e = 0; e < 4; ++e) acc[mi][ni][e] = 0.f;

    const int a_row = (lane & 15);
    const int a_koff = (lane >> 4) * 8;
    const int b_row = (lane & 7) + ((lane >> 4) * 8);
    const int b_koff = ((lane >> 3) & 1) * 8;

    load_stage_out(smb, mbase, nbase, 0, 0, tid);
    CP_COMMIT();

    for (int ck = 0; ck < NCHUNK; ++ck) {
        const int buf = ck & 1;
        cp_wait<0>();
        __syncthreads();
        if (ck + 1 < NCHUNK) {
            load_stage_out(smb, mbase, nbase, (ck + 1) * BK, buf ^ 1, tid);
            CP_COMMIT();
        }

        const uint32_t sA   = smb + buf * OSTAGE_BYTES;
        const uint32_t sBhi = sA + SPLIT_BYTES;
        const uint32_t sBlo = sA + 2 * SPLIT_BYTES;

#pragma unroll
        for (int ks = 0; ks < 2; ++ks) {
            const int k0 = ks * 16;
            uint32_t a[4][4];
#pragma unroll
            for (int mi = 0; mi < 4; ++mi) {
                uint32_t off = ((wm + mi * 16 + a_row) * SA + k0 + a_koff) * 2;
                ldmatrix_x4(a[mi], sA + off);
            }
            uint32_t bhi[2][4], blo[2][4];
#pragma unroll
            for (int bi = 0; bi < 2; ++bi) {
                uint32_t off = ((wn + bi * 16 + b_row) * SA + k0 + b_koff) * 2;
                ldmatrix_x4(bhi[bi], sBhi + off);
                ldmatrix_x4(blo[bi], sBlo + off);
            }
#pragma unroll
            for (int mi = 0; mi < 4; ++mi) {
#pragma unroll
                for (int ni = 0; ni < 4; ++ni) {
                    const int g = ni >> 1, h = (ni & 1) * 2;
                    mma_16816_f16(acc[mi][ni], a[mi], bhi[g][h], bhi[g][h + 1]);
                    mma_16816_f16(acc[mi][ni], a[mi], blo[g][h], blo[g][h + 1]);
                }
            }
        }
    }

    const int fr = lane >> 2;
    const int fc = (lane & 3) * 2;
#pragma unroll
    for (int mi = 0; mi < 4; ++mi) {
#pragma unroll
        for (int ni = 0; ni < 4; ++ni) {
            const int col = nbase + wn + ni * 8 + fc;
            const float b0 = bo[col], b1 = bo[col + 1];
            const int row0 = mbase + wm + mi * 16 + fr;
            float* p0 = out + (size_t)row0 * EMB + col;
            float* p1 = out + (size_t)(row0 + 8) * EMB + col;
            p0[0] = acc[mi][ni][0] + b0;
            p0[1] = acc[mi][ni][1] + b1;
            p1[0] = acc[mi][ni][2] + b0;
            p1[1] = acc[mi][ni][3] + b1;
        }
    }
}

// ================= Flash attention via HMMA =================
// Br=128, Bc=64, diagonal-paired: CTA p handles q-tiles {7-p, p} (18 j-iters).
// S path: bf16 3-term; PV path: P fp16 single x V fp16 hi/lo (2-term).
#define ASTR 72
#define Q_BYTES    (128 * ASTR * 2)          // 18432 per split
#define KVBUF      (4 * 64 * ASTR * 2)       // 36864: Kh,Kl,Vh,Vl
#define ATTN_SMEM  (2 * Q_BYTES + 2 * KVBUF) // 110592

__device__ __forceinline__ void attn_load_kv(uint32_t kvbase, size_t gbase, int jb, int tid)
{
#pragma unroll
    for (int i = 0; i < 2; ++i) {
        int idx = tid + i * 256;
        int r = idx >> 3, seg = idx & 7;
        const size_t g = gbase + (size_t)(jb * 64 + r) * HDIM + seg * 8;
        const uint32_t so = (r * ASTR + seg * 8) * 2;
        cp_async16(kvbase + so,                  g_Khi + g);
        cp_async16(kvbase + 64 * ASTR * 2 + so,  g_Klo + g);
        cp_async16(kvbase + 128 * ASTR * 2 + so, g_Vhi + g);
        cp_async16(kvbase + 192 * ASTR * 2 + so, g_Vlo + g);
    }
}

__global__ __launch_bounds__(256, 2) void attn_mma_kernel()
{
    extern __shared__ char smraw[];
    const uint32_t uQh = smem_u32(smraw);
    const uint32_t uQl = uQh + Q_BYTES;
    const uint32_t uKV0 = uQl + Q_BYTES;

    const int tid = threadIdx.x, wid = tid >> 5, lane = tid & 31;
    const int pp = blockIdx.x;           // 0..3 (pair index)
    const int bh = blockIdx.y;           // 0..63
    const size_t gbase = (size_t)bh * SEQ * HDIM;

    const int a_row = lane & 15;
    const int a_koff = (lane >> 4) * 8;
    const int b_row = (lane & 7) + ((lane >> 4) * 8);
    const int b_koff = ((lane >> 3) & 1) * 8;

#pragma unroll
    for (int t = 0; t < 2; ++t) {
        const int qb = (t == 0) ? (7 - pp) : pp;
        if (t) __syncthreads();          // all warps done reading old Q/KV smem

        // ---- load Q tile (128 x 64) hi/lo ----
#pragma unroll
        for (int i = 0; i < 4; ++i) {
            int idx = tid + i * 256;
            int r = idx >> 3, seg = idx & 7;
            const size_t g = gbase + (size_t)(qb * 128 + r) * HDIM + seg * 8;
            const uint32_t so = (r * ASTR + seg * 8) * 2;
            cp_async16(uQh + so, g_Qhi + g);
            cp_async16(uQl + so, g_Qlo + g);
        }
        CP_COMMIT();
        attn_load_kv(uKV0, gbase, 0, tid);
        CP_COMMIT();

        float o[8][4];
#pragma unroll
        for (int nt = 0; nt < 8; ++nt)
#pragma unroll
            for (int e = 0; e < 4; ++e) o[nt][e] = 0.f;
        float m0 = -1e30f, m1 = -1e30f, l0 = 0.f, l1 = 0.f;

        const int r0g = qb * 128 + wid * 16 + (lane >> 2);

        const int jmax = 2 * qb + 1;
        for (int jb = 0; jb <= jmax; ++jb) {
            const uint32_t kvb = uKV0 + (jb & 1) * KVBUF;
            cp_wait<0>();
            __syncthreads();
            if (jb < jmax) {
                attn_load_kv(uKV0 + ((jb + 1) & 1) * KVBUF, gbase, jb + 1, tid);
                CP_COMMIT();
            }
            const uint32_t uKh = kvb;
            const uint32_t uKl = kvb + 64 * ASTR * 2;
            const uint32_t uVh = kvb + 128 * ASTR * 2;
            const uint32_t uVl = kvb + 192 * ASTR * 2;

            // ---- S = Q @ K^T (bf16 3-term; Q pre-scaled by 0.5) ----
            float s[8][4];
#pragma unroll
            for (int nt = 0; nt < 8; ++nt)
#pragma unroll
                for (int e = 0; e < 4; ++e) s[nt][e] = 0.f;

#pragma unroll
            for (int ks = 0; ks < 4; ++ks) {
                uint32_t qh[4], ql[4];
                {
                    uint32_t off = ((wid * 16 + a_row) * ASTR + ks * 16 + a_koff) * 2;
                    ldmatrix_x4(qh, uQh + off);
                    ldmatrix_x4(ql, uQl + off);
                }
                uint32_t kh[4][4], kl[4][4];
#pragma unroll
                for (int g = 0; g < 4; ++g) {
                    uint32_t off = ((g * 16 + b_row) * ASTR + ks * 16 + b_koff) * 2;
                    ldmatrix_x4(kh[g], uKh + off);
                    ldmatrix_x4(kl[g], uKl + off);
                }
#pragma unroll
                for (int g = 0; g < 4; ++g) {
#pragma unroll
                    for (int hh = 0; hh < 2; ++hh) {
                        const int nt = 2 * g + hh;
                        mma_16816(s[nt], qh, kh[g][hh * 2], kh[g][hh * 2 + 1]);
                        mma_16816(s[nt], qh, kl[g][hh * 2], kl[g][hh * 2 + 1]);
                        mma_16816(s[nt], ql, kh[g][hh * 2], kh[g][hh * 2 + 1]);
                    }
                }
            }

            // ---- causal mask + online softmax (scale already folded into Q) ----
            const bool needmask = (jb >= 2 * qb);
            float mx0 = -1e30f, mx1 = -1e30f;
#pragma unroll
            for (int nt = 0; nt < 8; ++nt) {
                if (needmask) {
                    const int c = jb * 64 + nt * 8 + (lane & 3) * 2;
                    s[nt][0] = (c     <= r0g)     ? s[nt][0] : -1e30f;
                    s[nt][1] = (c + 1 <= r0g)     ? s[nt][1] : -1e30f;
                    s[nt][2] = (c     <= r0g + 8) ? s[nt][2] : -1e30f;
                    s[nt][3] = (c + 1 <= r0g + 8) ? s[nt][3] : -1e30f;
                }
                mx0 = fmaxf(mx0, fmaxf(s[nt][0], s[nt][1]));
                mx1 = fmaxf(mx1, fmaxf(s[nt][2], s[nt][3]));
            }
            mx0 = fmaxf(mx0, __shfl_xor_sync(0xffffffffu, mx0, 1));
            mx0 = fmaxf(mx0, __shfl_xor_sync(0xffffffffu, mx0, 2));
            mx1 = fmaxf(mx1, __shfl_xor_sync(0xffffffffu, mx1, 1));
            mx1 = fmaxf(mx1, __shfl_xor_sync(0xffffffffu, mx1, 2));

            const float nm0 = fmaxf(m0, mx0), nm1 = fmaxf(m1, mx1);
            const float al0 = __expf(m0 - nm0), al1 = __expf(m1 - nm1);
            m0 = nm0; m1 = nm1;

            float rs0 = 0.f, rs1 = 0.f;
#pragma unroll
            for (int nt = 0; nt < 8; ++nt) {
                s[nt][0] = __expf(s[nt][0] - m0);
                s[nt][1] = __expf(s[nt][1] - m0);
                s[nt][2] = __expf(s[nt][2] - m1);
                s[nt][3] = __expf(s[nt][3] - m1);
                rs0 += s[nt][0] + s[nt][1];
                rs1 += s[nt][2] + s[nt][3];
            }
            rs0 += __shfl_xor_sync(0xffffffffu, rs0, 1);
            rs0 += __shfl_xor_sync(0xffffffffu, rs0, 2);
            rs1 += __shfl_xor_sync(0xffffffffu, rs1, 1);
            rs1 += __shfl_xor_sync(0xffffffffu, rs1, 2);
            l0 = l0 * al0 + rs0;
            l1 = l1 * al1 + rs1;

#pragma unroll
            for (int nt = 0; nt < 8; ++nt) {
                o[nt][0] *= al0; o[nt][1] *= al0;
                o[nt][2] *= al1; o[nt][3] *= al1;
            }

            // ---- O += P @ V (P fp16 single; V fp16 hi/lo, 2-term) ----
#pragma unroll
            for (int ks = 0; ks < 4; ++ks) {
                uint32_t ph[4];
                ph[0] = packh2(s[2 * ks][0],     s[2 * ks][1]);
                ph[1] = packh2(s[2 * ks][2],     s[2 * ks][3]);
                ph[2] = packh2(s[2 * ks + 1][0], s[2 * ks + 1][1]);
                ph[3] = packh2(s[2 * ks + 1][2], s[2 * ks + 1][3]);

                uint32_t vh[4][4], vl[4][4];
#pragma unroll
                for (int dg = 0; dg < 4; ++dg) {
                    uint32_t off = (((lane & 15) + ks * 16) * ASTR + dg * 16 + (lane >> 4) * 8) * 2;
                    ldmatrix_x4_trans(vh[dg], uVh + off);
                    ldmatrix_x4_trans(vl[dg], uVl + off);
                }
#pragma unroll
                for (int dg = 0; dg < 4; ++dg) {
#pragma unroll
                    for (int hh = 0; hh < 2; ++hh) {
                        const int nt = 2 * dg + hh;
                        mma_16816_f16(o[nt], ph, vh[dg][hh * 2], vh[dg][hh * 2 + 1]);
                        mma_16816_f16(o[nt], ph, vl[dg][hh * 2], vl[dg][hh * 2 + 1]);
                    }
                }
            }
        }

        // ---- normalize + write Z (single fp16, [B,H,S,Dh] flat) ----
        const float inv0 = 1.f / l0, inv1 = 1.f / l1;
        const int r0 = wid * 16 + (lane >> 2);
        const size_t zr0 = ((size_t)bh * SEQ + (size_t)qb * 128 + r0) * HDIM;
        const size_t zr1 = zr0 + 8 * HDIM;
#pragma unroll
        for (int nt = 0; nt < 8; ++nt) {
            const int c = nt * 8 + (lane & 3) * 2;
            *(uint32_t*)(g_Z + zr0 + c) = packh2(o[nt][0] * inv0, o[nt][1] * inv0);
            *(uint32_t*)(g_Z + zr1 + c) = packh2(o[nt][2] * inv1, o[nt][3] * inv1);
        }
    }
}

// ---------------- launch ----------------
extern "C" void kernel_launch(void* const* d_in, const int* in_sizes, int n_in,
                              void* d_out, int out_size)
{
    const float* X  = (const float*)d_in[0];
    const float* wq = (const float*)d_in[2];
    const float* bq = (const float*)d_in[3];
    const float* wk = (const float*)d_in[4];
    const float* bk = (const float*)d_in[5];
    const float* wv = (const float*)d_in[6];
    const float* bv = (const float*)d_in[7];
    const float* wo = (const float*)d_in[8];
    const float* bo = (const float*)d_in[9];
    float* out = (float*)d_out;

    __nv_bfloat16 *Xhi, *Xlo;
    cudaGetSymbolAddress((void**)&Xhi, g_Xhi);
    cudaGetSymbolAddress((void**)&Xlo, g_Xlo);

    cudaFuncSetAttribute(attn_mma_kernel, cudaFuncAttributeMaxDynamicSharedMemorySize, ATTN_SMEM);
    cudaFuncSetAttribute(qkv_mma_kernel, cudaFuncAttributeMaxDynamicSharedMemorySize, GEMM_SMEM);
    cudaFuncSetAttribute(out_mma_kernel, cudaFuncAttributeMaxDynamicSharedMemorySize, OGEMM_SMEM);

    // split X into bf16 hi/lo; split+transpose 4 weight matrices (wo -> fp16)
    cvt_split_kernel<<<(MROWS * EMB / 4) / 256, 256>>>(X, Xhi, Xlo);
    cvt_splitT_kernel<<<dim3(EMB / 32, EMB / 32, 4), 256>>>(wq, wk, wv, wo);

    // QKV projections (z: 0=Q(x0.5,bf16) 1=K(bf16) 2=V(fp16)), per-head layout
    qkv_mma_kernel<<<dim3(EMB / 128, MROWS / 128, 3), 256, GEMM_SMEM>>>(bq, bk, bv);

    // causal flash attention, diagonal-paired -> g_Z (fp16)
    attn_mma_kernel<<<dim3(4, BATCH * HEADS), 256, ATTN_SMEM>>>();

    // output projection: fp16 2-term
    out_mma_kernel<<<dim3(EMB / 128, MROWS / 128), 256, OGEMM_SMEM>>>(bo, out);

    (void)in_sizes; (void)n_in; (void)out_size;
}

// round 9
// speedup vs baseline: 3.1682x; 1.0027x over previous
#include <cuda_runtime.h>
#include <cuda_bf16.h>
#include <cuda_fp16.h>
#include <cstdint>

// Problem constants
#define BATCH   4
#define SEQ     1024
#define EMB     1024
#define HEADS   16
#define HDIM    64
#define MROWS   (BATCH * SEQ)      // 4096

// ---------------- scratch (16B-aligned for cp.async) ----------------
__device__ __align__(256) __nv_bfloat16 g_Xhi[MROWS * EMB];
__device__ __align__(256) __nv_bfloat16 g_Xlo[MROWS * EMB];
// Q/K in per-head layout [B, H, S, HDIM], bf16 hi/lo; V fp16 hi/lo
__device__ __align__(256) __nv_bfloat16 g_Qhi[MROWS * EMB];
__device__ __align__(256) __nv_bfloat16 g_Qlo[MROWS * EMB];
__device__ __align__(256) __nv_bfloat16 g_Khi[MROWS * EMB];
__device__ __align__(256) __nv_bfloat16 g_Klo[MROWS * EMB];
__device__ __align__(256) __half       g_Vhi[MROWS * EMB];
__device__ __align__(256) __half       g_Vlo[MROWS * EMB];
// Z single fp16 ([B,H,S,Dh] flat = [MROWS, EMB] row-major view)
__device__ __align__(256) __half       g_Z[MROWS * EMB];
// wq,wk,wv transposed [N,K] bf16 hi/lo; wo transposed [N,K] fp16 hi/lo
__device__ __align__(256) __nv_bfloat16 g_Whi[3 * EMB * EMB];
__device__ __align__(256) __nv_bfloat16 g_Wlo[3 * EMB * EMB];
__device__ __align__(256) __half       g_WOhi[EMB * EMB];
__device__ __align__(256) __half       g_WOlo[EMB * EMB];

// ================= PTX helpers (sm_80+ subset only) =============
__device__ __forceinline__ uint32_t smem_u32(const void* p) {
    uint32_t a;
    asm("{ .reg .u64 t; cvta.to.shared.u64 t, %1; cvt.u32.u64 %0, t; }" : "=r"(a) : "l"(p));
    return a;
}

__device__ __forceinline__ void cp_async16(uint32_t saddr, const void* gaddr) {
    asm volatile("cp.async.cg.shared.global [%0], [%1], 16;" :: "r"(saddr), "l"(gaddr));
}
#define CP_COMMIT()  asm volatile("cp.async.commit_group;" ::: "memory")
template <int N>
__device__ __forceinline__ void cp_wait() {
    asm volatile("cp.async.wait_group %0;" :: "n"(N) : "memory");
}

__device__ __forceinline__ void ldmatrix_x4(uint32_t (&r)[4], uint32_t addr) {
    asm volatile("ldmatrix.sync.aligned.m8n8.x4.shared.b16 {%0,%1,%2,%3}, [%4];"
                 : "=r"(r[0]), "=r"(r[1]), "=r"(r[2]), "=r"(r[3]) : "r"(addr));
}
__device__ __forceinline__ void ldmatrix_x4_trans(uint32_t (&r)[4], uint32_t addr) {
    asm volatile("ldmatrix.sync.aligned.m8n8.x4.trans.shared.b16 {%0,%1,%2,%3}, [%4];"
                 : "=r"(r[0]), "=r"(r[1]), "=r"(r[2]), "=r"(r[3]) : "r"(addr));
}

__device__ __forceinline__ void mma_16816(float (&d)[4], const uint32_t (&a)[4],
                                          uint32_t b0, uint32_t b1) {
    asm volatile(
        "mma.sync.aligned.m16n8k16.row.col.f32.bf16.bf16.f32 "
        "{%0,%1,%2,%3}, {%4,%5,%6,%7}, {%8,%9}, {%0,%1,%2,%3};"
        : "+f"(d[0]), "+f"(d[1]), "+f"(d[2]), "+f"(d[3])
        : "r"(a[0]), "r"(a[1]), "r"(a[2]), "r"(a[3]), "r"(b0), "r"(b1));
}
__device__ __forceinline__ void mma_16816_f16(float (&d)[4], const uint32_t (&a)[4],
                                              uint32_t b0, uint32_t b1) {
    asm volatile(
        "mma.sync.aligned.m16n8k16.row.col.f32.f16.f16.f32 "
        "{%0,%1,%2,%3}, {%4,%5,%6,%7}, {%8,%9}, {%0,%1,%2,%3};"
        : "+f"(d[0]), "+f"(d[1]), "+f"(d[2]), "+f"(d[3])
        : "r"(a[0]), "r"(a[1]), "r"(a[2]), "r"(a[3]), "r"(b0), "r"(b1));
}

// fp32 pair -> packed bf16x2 hi + lo
__device__ __forceinline__ void split2(float x, float y, uint32_t& hi, uint32_t& lo) {
    __nv_bfloat16 hx = __float2bfloat16(x);
    __nv_bfloat16 hy = __float2bfloat16(y);
    __nv_bfloat16 lx = __float2bfloat16(x - __bfloat162float(hx));
    __nv_bfloat16 ly = __float2bfloat16(y - __bfloat162float(hy));
    __nv_bfloat162 hp(hx, hy), lp(lx, ly);
    hi = *(uint32_t*)&hp;
    lo = *(uint32_t*)&lp;
}
// fp32 pair -> packed fp16x2 hi + lo
__device__ __forceinline__ void split2h(float x, float y, uint32_t& hi, uint32_t& lo) {
    __half hx = __float2half_rn(x);
    __half hy = __float2half_rn(y);
    __half lx = __float2half_rn(x - __half2float(hx));
    __half ly = __float2half_rn(y - __half2float(hy));
    __half2 hp(hx, hy), lp(lx, ly);
    hi = *(uint32_t*)&hp;
    lo = *(uint32_t*)&lp;
}
__device__ __forceinline__ uint32_t packh2(float x, float y) {
    __half2 h = __floats2half2_rn(x, y);
    return *(uint32_t*)&h;
}

// ================= conversion kernels =================
__global__ __launch_bounds__(256) void cvt_split_kernel(
    const float* __restrict__ src, __nv_bfloat16* __restrict__ hi,
    __nv_bfloat16* __restrict__ lo)
{
    int i = blockIdx.x * blockDim.x + threadIdx.x;     // one float4 each
    float4 v = ((const float4*)src)[i];
    uint32_t h0, l0, h1, l1;
    split2(v.x, v.y, h0, l0);
    split2(v.z, v.w, h1, l1);
    ((uint2*)hi)[i] = make_uint2(h0, h1);
    ((uint2*)lo)[i] = make_uint2(l0, l1);
}

// W [K,N] fp32 -> WT [N,K] hi/lo (transpose+split). z<3: bf16; z==3: fp16.
__global__ __launch_bounds__(256) void cvt_splitT_kernel(
    const float* __restrict__ w0, const float* __restrict__ w1,
    const float* __restrict__ w2, const float* __restrict__ w3)
{
    __shared__ float t[32][33];
    const int z = blockIdx.z;
    const float* W = (z == 0) ? w0 : (z == 1) ? w1 : (z == 2) ? w2 : w3;
    const int bx = blockIdx.x * 32;   // N base
    const int by = blockIdx.y * 32;   // K base
    const int tx = threadIdx.x & 31;
    const int ty = threadIdx.x >> 5;  // 0..7
    for (int i = ty; i < 32; i += 8)
        t[i][tx] = W[(size_t)(by + i) * EMB + bx + tx];
    __syncthreads();
    if (z < 3) {
        __nv_bfloat16* hiT = g_Whi + (size_t)z * EMB * EMB;
        __nv_bfloat16* loT = g_Wlo + (size_t)z * EMB * EMB;
        for (int i = ty; i < 32; i += 8) {
            float v = t[tx][i];
            __nv_bfloat16 h = __float2bfloat16(v);
            __nv_bfloat16 l = __float2bfloat16(v - __bfloat162float(h));
            hiT[(size_t)(bx + i) * EMB + by + tx] = h;
            loT[(size_t)(bx + i) * EMB + by + tx] = l;
        }
    } else {
        for (int i = ty; i < 32; i += 8) {
            float v = t[tx][i];
            __half h = __float2half_rn(v);
            __half l = __float2half_rn(v - __half2float(h));
            g_WOhi[(size_t)(bx + i) * EMB + by + tx] = h;
            g_WOlo[(size_t)(bx + i) * EMB + by + tx] = l;
        }
    }
}

// ================= HMMA bf16x3 QKV GEMM =================
#define BK          32
#define NCHUNK      (EMB / BK)              // 32
#define SA          40                       // smem row stride (elems)
#define SPLIT_BYTES (128 * SA * 2)          // 10240
#define STAGE_BYTES (4 * SPLIT_BYTES)       // 40960
#define GEMM_SMEM   (2 * STAGE_BYTES)       // 81920

// Q pre-scale: 1/16^0.25 * log2(e)  (softmax done in exp2 domain)
#define QSCALE (0.5f * 1.4426950408889634f)

__device__ __forceinline__ void load_stage_async(
    uint32_t smb, const __nv_bfloat16* __restrict__ Ahi, const __nv_bfloat16* __restrict__ Alo,
    const __nv_bfloat16* __restrict__ Bhi, const __nv_bfloat16* __restrict__ Blo,
    int mbase, int nbase, int k0, int buf, int tid)
{
    const __nv_bfloat16* gsrc[4] = {
        Ahi + (size_t)mbase * EMB + k0, Alo + (size_t)mbase * EMB + k0,
        Bhi + (size_t)nbase * EMB + k0, Blo + (size_t)nbase * EMB + k0 };
    const uint32_t sbase = smb + buf * STAGE_BYTES;
#pragma unroll
    for (int m = 0; m < 4; ++m) {
#pragma unroll
        for (int i = 0; i < 2; ++i) {
            int idx = tid + i * 256;
            int r = idx >> 2, seg = idx & 3;
            uint32_t sa = sbase + m * SPLIT_BYTES + (r * SA + seg * 8) * 2;
            cp_async16(sa, gsrc[m] + (size_t)r * EMB + seg * 8);
        }
    }
}

// mode 0: Q (bf16 split, xQSCALE); mode 1: K (bf16 split); mode 2: V (fp16 split)
__global__ __launch_bounds__(256, 2)
void qkv_mma_kernel(const float* __restrict__ bq, const float* __restrict__ bk,
                    const float* __restrict__ bv)
{
    extern __shared__ char sm[];
    const uint32_t smb = smem_u32(sm);
    const int tid  = threadIdx.x;
    const int wid  = tid >> 5;
    const int lane = tid & 31;
    const int mbase = blockIdx.y * 128;
    const int nbase = blockIdx.x * 128;
    const int mode = blockIdx.z;

    const __nv_bfloat16* Bh = g_Whi + (size_t)mode * EMB * EMB;
    const __nv_bfloat16* Bl = g_Wlo + (size_t)mode * EMB * EMB;
    const float* bias = (mode == 0) ? bq : (mode == 1) ? bk : bv;

    const int wm = (wid & 1) * 64;
    const int wn = (wid >> 1) * 32;

    float acc[4][4][4];
#pragma unroll
    for (int mi = 0; mi < 4; ++mi)
#pragma unroll
        for (int ni = 0; ni < 4; ++ni)
#pragma unroll
            for (int e = 0; e < 4; ++e) acc[mi][ni][e] = 0.f;

    const int a_row = (lane & 15);
    const int a_koff = (lane >> 4) * 8;
    const int b_row = (lane & 7) + ((lane >> 4) * 8);
    const int b_koff = ((lane >> 3) & 1) * 8;

    load_stage_async(smb, g_Xhi, g_Xlo, Bh, Bl, mbase, nbase, 0, 0, tid);
    CP_COMMIT();

    for (int ck = 0; ck < NCHUNK; ++ck) {
        const int buf = ck & 1;
        cp_wait<0>();
        __syncthreads();
        if (ck + 1 < NCHUNK) {
            load_stage_async(smb, g_Xhi, g_Xlo, Bh, Bl, mbase, nbase, (ck + 1) * BK, buf ^ 1, tid);
            CP_COMMIT();
        }

        const uint32_t sAhi = smb + buf * STAGE_BYTES;
        const uint32_t sAlo = sAhi + SPLIT_BYTES;
        const uint32_t sBhi = sAhi + 2 * SPLIT_BYTES;
        const uint32_t sBlo = sAhi + 3 * SPLIT_BYTES;

#pragma unroll
        for (int ks = 0; ks < 2; ++ks) {
            const int k0 = ks * 16;
            uint32_t ahi[4][4], alo[4][4];
#pragma unroll
            for (int mi = 0; mi < 4; ++mi) {
                uint32_t off = ((wm + mi * 16 + a_row) * SA + k0 + a_koff) * 2;
                ldmatrix_x4(ahi[mi], sAhi + off);
                ldmatrix_x4(alo[mi], sAlo + off);
            }
            uint32_t bhi[2][4], blo[2][4];
#pragma unroll
            for (int bi = 0; bi < 2; ++bi) {
                uint32_t off = ((wn + bi * 16 + b_row) * SA + k0 + b_koff) * 2;
                ldmatrix_x4(bhi[bi], sBhi + off);
                ldmatrix_x4(blo[bi], sBlo + off);
            }
            // term-major: 16 independent accumulators between same-acc reuses
#pragma unroll
            for (int mi = 0; mi < 4; ++mi)
#pragma unroll
                for (int ni = 0; ni < 4; ++ni) {
                    const int g = ni >> 1, h = (ni & 1) * 2;
                    mma_16816(acc[mi][ni], ahi[mi], bhi[g][h], bhi[g][h + 1]);
                }
#pragma unroll
            for (int mi = 0; mi < 4; ++mi)
#pragma unroll
                for (int ni = 0; ni < 4; ++ni) {
                    const int g = ni >> 1, h = (ni & 1) * 2;
                    mma_16816(acc[mi][ni], ahi[mi], blo[g][h], blo[g][h + 1]);
                }
#pragma unroll
            for (int mi = 0; mi < 4; ++mi)
#pragma unroll
                for (int ni = 0; ni < 4; ++ni) {
                    const int g = ni >> 1, h = (ni & 1) * 2;
                    mma_16816(acc[mi][ni], alo[mi], bhi[g][h], bhi[g][h + 1]);
                }
        }
    }

    const int fr = lane >> 2;
    const int fc = (lane & 3) * 2;
    const float qscale = (mode == 0) ? QSCALE : 1.0f;
#pragma unroll
    for (int mi = 0; mi < 4; ++mi) {
#pragma unroll
        for (int ni = 0; ni < 4; ++ni) {
            const int col = nbase + wn + ni * 8 + fc;
            const float b0 = bias[col], b1 = bias[col + 1];
            const int row0 = mbase + wm + mi * 16 + fr;
            const float v0 = (acc[mi][ni][0] + b0) * qscale;
            const float v1 = (acc[mi][ni][1] + b1) * qscale;
            const float v2 = (acc[mi][ni][2] + b0) * qscale;
            const float v3 = (acc[mi][ni][3] + b1) * qscale;
            // per-head layout: row0 = b*1024 + s ; col = h*64 + d
            const int bb = row0 >> 10, ss = row0 & 1023;
            const int hh = col >> 6,  dd = col & 63;
            const size_t dst = (((size_t)bb * HEADS + hh) * SEQ + ss) * HDIM + dd;
            if (mode == 2) {
                uint32_t h01, l01, h23, l23;
                split2h(v0, v1, h01, l01);
                split2h(v2, v3, h23, l23);
                *(uint32_t*)(g_Vhi + dst)            = h01;
                *(uint32_t*)(g_Vlo + dst)            = l01;
                *(uint32_t*)(g_Vhi + dst + 8 * HDIM) = h23;
                *(uint32_t*)(g_Vlo + dst + 8 * HDIM) = l23;
            } else {
                __nv_bfloat16* Chi = (mode == 0) ? g_Qhi : g_Khi;
                __nv_bfloat16* Clo = (mode == 0) ? g_Qlo : g_Klo;
                uint32_t h01, l01, h23, l23;
                split2(v0, v1, h01, l01);
                split2(v2, v3, h23, l23);
                *(uint32_t*)(Chi + dst)            = h01;
                *(uint32_t*)(Clo + dst)            = l01;
                *(uint32_t*)(Chi + dst + 8 * HDIM) = h23;
                *(uint32_t*)(Clo + dst + 8 * HDIM) = l23;
            }
        }
    }
}

// ================= out projection: fp16 2-term (Z single, Wo hi/lo) ========
#define OSTAGE_BYTES (3 * SPLIT_BYTES)       // 30720: A, Bhi, Blo
#define OGEMM_SMEM   (2 * OSTAGE_BYTES)      // 61440

__device__ __forceinline__ void load_stage_out(
    uint32_t smb, int mbase, int nbase, int k0, int buf, int tid)
{
    const __half* gsrc[3] = {
        g_Z    + (size_t)mbase * EMB + k0,
        g_WOhi + (size_t)nbase * EMB + k0,
        g_WOlo + (size_t)nbase * EMB + k0 };
    const uint32_t sbase = smb + buf * OSTAGE_BYTES;
#pragma unroll
    for (int m = 0; m < 3; ++m) {
#pragma unroll
        for (int i = 0; i < 2; ++i) {
            int idx = tid + i * 256;
            int r = idx >> 2, seg = idx & 3;
            uint32_t sa = sbase + m * SPLIT_BYTES + (r * SA + seg * 8) * 2;
            cp_async16(sa, gsrc[m] + (size_t)r * EMB + seg * 8);
        }
    }
}

__global__ __launch_bounds__(256, 2)
void out_mma_kernel(const float* __restrict__ bo, float* __restrict__ out)
{
    extern __shared__ char sm[];
    const uint32_t smb = smem_u32(sm);
    const int tid  = threadIdx.x;
    const int wid  = tid >> 5;
    const int lane = tid & 31;
    const int mbase = blockIdx.y * 128;
    const int nbase = blockIdx.x * 128;

    const int wm = (wid & 1) * 64;
    const int wn = (wid >> 1) * 32;

    float acc[4][4][4];
#pragma unroll
    for (int mi = 0; mi < 4; ++mi)
#pragma unroll
        for (int ni = 0; ni < 4; ++ni)
#pragma unroll
            for (int e = 0; e < 4; ++e) acc[mi][ni][e] = 0.f;

    const int a_row = (lane & 15);
    const int a_koff = (lane >> 4) * 8;
    const int b_row = (lane & 7) + ((lane >> 4) * 8);
    const int b_koff = ((lane >> 3) & 1) * 8;

    load_stage_out(smb, mbase, nbase, 0, 0, tid);
    CP_COMMIT();

    for (int ck = 0; ck < NCHUNK; ++ck) {
        const int buf = ck & 1;
        cp_wait<0>();
        __syncthreads();
        if (ck + 1 < NCHUNK) {
            load_stage_out(smb, mbase, nbase, (ck + 1) * BK, buf ^ 1, tid);
            CP_COMMIT();
        }

        const uint32_t sA   = smb + buf * OSTAGE_BYTES;
        const uint32_t sBhi = sA + SPLIT_BYTES;
        const uint32_t sBlo = sA + 2 * SPLIT_BYTES;

#pragma unroll
        for (int ks = 0; ks < 2; ++ks) {
            const int k0 = ks * 16;
            uint32_t a[4][4];
#pragma unroll
            for (int mi = 0; mi < 4; ++mi) {
                uint32_t off = ((wm + mi * 16 + a_row) * SA + k0 + a_koff) * 2;
                ldmatrix_x4(a[mi], sA + off);
            }
            uint32_t bhi[2][4], blo[2][4];
#pragma unroll
            for (int bi = 0; bi < 2; ++bi) {
                uint32_t off = ((wn + bi * 16 + b_row) * SA + k0 + b_koff) * 2;
                ldmatrix_x4(bhi[bi], sBhi + off);
                ldmatrix_x4(blo[bi], sBlo + off);
            }
            // term-major
#pragma unroll
            for (int mi = 0; mi < 4; ++mi)
#pragma unroll
                for (int ni = 0; ni < 4; ++ni) {
                    const int g = ni >> 1, h = (ni & 1) * 2;
                    mma_16816_f16(acc[mi][ni], a[mi], bhi[g][h], bhi[g][h + 1]);
                }
#pragma unroll
            for (int mi = 0; mi < 4; ++mi)
#pragma unroll
                for (int ni = 0; ni < 4; ++ni) {
                    const int g = ni >> 1, h = (ni & 1) * 2;
                    mma_16816_f16(acc[mi][ni], a[mi], blo[g][h], blo[g][h + 1]);
                }
        }
    }

    const int fr = lane >> 2;
    const int fc = (lane & 3) * 2;
#pragma unroll
    for (int mi = 0; mi < 4; ++mi) {
#pragma unroll
        for (int ni = 0; ni < 4; ++ni) {
            const int col = nbase + wn + ni * 8 + fc;
            const float b0 = bo[col], b1 = bo[col + 1];
            const int row0 = mbase + wm + mi * 16 + fr;
            float* p0 = out + (size_t)row0 * EMB + col;
            float* p1 = out + (size_t)(row0 + 8) * EMB + col;
            p0[0] = acc[mi][ni][0] + b0;
            p0[1] = acc[mi][ni][1] + b1;
            p1[0] = acc[mi][ni][2] + b0;
            p1[1] = acc[mi][ni][3] + b1;
        }
    }
}

// ================= Flash attention via HMMA =================
// Br=128, Bc=64, diagonal-paired: CTA p handles q-tiles {7-p, p} (18 j-iters).
// S path: bf16 3-term (exp2 domain); PV path: P fp16 single x V fp16 hi/lo.
#define ASTR 72
#define Q_BYTES    (128 * ASTR * 2)          // 18432 per split
#define KVBUF      (4 * 64 * ASTR * 2)       // 36864: Kh,Kl,Vh,Vl
#define ATTN_SMEM  (2 * Q_BYTES + 2 * KVBUF) // 110592

__device__ __forceinline__ void attn_load_kv(uint32_t kvbase, size_t gbase, int jb, int tid)
{
#pragma unroll
    for (int i = 0; i < 2; ++i) {
        int idx = tid + i * 256;
        int r = idx >> 3, seg = idx & 7;
        const size_t g = gbase + (size_t)(jb * 64 + r) * HDIM + seg * 8;
        const uint32_t so = (r * ASTR + seg * 8) * 2;
        cp_async16(kvbase + so,                  g_Khi + g);
        cp_async16(kvbase + 64 * ASTR * 2 + so,  g_Klo + g);
        cp_async16(kvbase + 128 * ASTR * 2 + so, g_Vhi + g);
        cp_async16(kvbase + 192 * ASTR * 2 + so, g_Vlo + g);
    }
}

__global__ __launch_bounds__(256, 2) void attn_mma_kernel()
{
    extern __shared__ char smraw[];
    const uint32_t uQh = smem_u32(smraw);
    const uint32_t uQl = uQh + Q_BYTES;
    const uint32_t uKV0 = uQl + Q_BYTES;

    const int tid = threadIdx.x, wid = tid >> 5, lane = tid & 31;
    const int pp = blockIdx.x;           // 0..3 (pair index)
    const int bh = blockIdx.y;           // 0..63
    const size_t gbase = (size_t)bh * SEQ * HDIM;

    const int a_row = lane & 15;
    const int a_koff = (lane >> 4) * 8;
    const int b_row = (lane & 7) + ((lane >> 4) * 8);
    const int b_koff = ((lane >> 3) & 1) * 8;

#pragma unroll
    for (int t = 0; t < 2; ++t) {
        const int qb = (t == 0) ? (7 - pp) : pp;
        if (t) __syncthreads();          // all warps done reading old Q/KV smem

        // ---- load Q tile (128 x 64) hi/lo ----
#pragma unroll
        for (int i = 0; i < 4; ++i) {
            int idx = tid + i * 256;
            int r = idx >> 3, seg = idx & 7;
            const size_t g = gbase + (size_t)(qb * 128 + r) * HDIM + seg * 8;
            const uint32_t so = (r * ASTR + seg * 8) * 2;
            cp_async16(uQh + so, g_Qhi + g);
            cp_async16(uQl + so, g_Qlo + g);
        }
        CP_COMMIT();
        attn_load_kv(uKV0, gbase, 0, tid);
        CP_COMMIT();

        float o[8][4];
#pragma unroll
        for (int nt = 0; nt < 8; ++nt)
#pragma unroll
            for (int e = 0; e < 4; ++e) o[nt][e] = 0.f;
        float m0 = -1e30f, m1 = -1e30f, l0 = 0.f, l1 = 0.f;

        const int r0g = qb * 128 + wid * 16 + (lane >> 2);

        const int jmax = 2 * qb + 1;
        for (int jb = 0; jb <= jmax; ++jb) {
            const uint32_t kvb = uKV0 + (jb & 1) * KVBUF;
            cp_wait<0>();
            __syncthreads();
            if (jb < jmax) {
                attn_load_kv(uKV0 + ((jb + 1) & 1) * KVBUF, gbase, jb + 1, tid);
                CP_COMMIT();
            }
            const uint32_t uKh = kvb;
            const uint32_t uKl = kvb + 64 * ASTR * 2;
            const uint32_t uVh = kvb + 128 * ASTR * 2;
            const uint32_t uVl = kvb + 192 * ASTR * 2;

            // ---- S = Q @ K^T (bf16 3-term, term-major; Q pre-scaled) ----
            float s[8][4];
#pragma unroll
            for (int nt = 0; nt < 8; ++nt)
#pragma unroll
                for (int e = 0; e < 4; ++e) s[nt][e] = 0.f;

#pragma unroll
            for (int ks = 0; ks < 4; ++ks) {
                uint32_t qh[4], ql[4];
                {
                    uint32_t off = ((wid * 16 + a_row) * ASTR + ks * 16 + a_koff) * 2;
                    ldmatrix_x4(qh, uQh + off);
                    ldmatrix_x4(ql, uQl + off);
                }
                uint32_t kh[4][4], kl[4][4];
#pragma unroll
                for (int g = 0; g < 4; ++g) {
                    uint32_t off = ((g * 16 + b_row) * ASTR + ks * 16 + b_koff) * 2;
                    ldmatrix_x4(kh[g], uKh + off);
                    ldmatrix_x4(kl[g], uKl + off);
                }
                // term-major: 8 independent accs per pass
#pragma unroll
                for (int g = 0; g < 4; ++g)
#pragma unroll
                    for (int hh = 0; hh < 2; ++hh)
                        mma_16816(s[2 * g + hh], qh, kh[g][hh * 2], kh[g][hh * 2 + 1]);
#pragma unroll
                for (int g = 0; g < 4; ++g)
#pragma unroll
                    for (int hh = 0; hh < 2; ++hh)
                        mma_16816(s[2 * g + hh], qh, kl[g][hh * 2], kl[g][hh * 2 + 1]);
#pragma unroll
                for (int g = 0; g < 4; ++g)
#pragma unroll
                    for (int hh = 0; hh < 2; ++hh)
                        mma_16816(s[2 * g + hh], ql, kh[g][hh * 2], kh[g][hh * 2 + 1]);
            }

            // ---- causal mask + online softmax in exp2 domain ----
            const bool needmask = (jb >= 2 * qb);
            float mx0 = -1e30f, mx1 = -1e30f;
#pragma unroll
            for (int nt = 0; nt < 8; ++nt) {
                if (needmask) {
                    const int c = jb * 64 + nt * 8 + (lane & 3) * 2;
                    s[nt][0] = (c     <= r0g)     ? s[nt][0] : -1e30f;
                    s[nt][1] = (c + 1 <= r0g)     ? s[nt][1] : -1e30f;
                    s[nt][2] = (c     <= r0g + 8) ? s[nt][2] : -1e30f;
                    s[nt][3] = (c + 1 <= r0g + 8) ? s[nt][3] : -1e30f;
                }
                mx0 = fmaxf(mx0, fmaxf(s[nt][0], s[nt][1]));
                mx1 = fmaxf(mx1, fmaxf(s[nt][2], s[nt][3]));
            }
            mx0 = fmaxf(mx0, __shfl_xor_sync(0xffffffffu, mx0, 1));
            mx0 = fmaxf(mx0, __shfl_xor_sync(0xffffffffu, mx0, 2));
            mx1 = fmaxf(mx1, __shfl_xor_sync(0xffffffffu, mx1, 1));
            mx1 = fmaxf(mx1, __shfl_xor_sync(0xffffffffu, mx1, 2));

            const float nm0 = fmaxf(m0, mx0), nm1 = fmaxf(m1, mx1);
            const float al0 = exp2f(m0 - nm0), al1 = exp2f(m1 - nm1);
            m0 = nm0; m1 = nm1;

#pragma unroll
            for (int nt = 0; nt < 8; ++nt) {
                o[nt][0] *= al0; o[nt][1] *= al0;
                o[nt][2] *= al1; o[nt][3] *= al1;
            }

            // ---- per-ks: exp2 + pack + PV (interleaves MUFU with tensor) ----
            float rs0 = 0.f, rs1 = 0.f;
#pragma unroll
            for (int ks = 0; ks < 4; ++ks) {
                float* sa = s[2 * ks];
                float* sb = s[2 * ks + 1];
                sa[0] = exp2f(sa[0] - m0);
                sa[1] = exp2f(sa[1] - m0);
                sa[2] = exp2f(sa[2] - m1);
                sa[3] = exp2f(sa[3] - m1);
                sb[0] = exp2f(sb[0] - m0);
                sb[1] = exp2f(sb[1] - m0);
                sb[2] = exp2f(sb[2] - m1);
                sb[3] = exp2f(sb[3] - m1);
                rs0 += sa[0] + sa[1] + sb[0] + sb[1];
                rs1 += sa[2] + sa[3] + sb[2] + sb[3];

                uint32_t ph[4];
                ph[0] = packh2(sa[0], sa[1]);
                ph[1] = packh2(sa[2], sa[3]);
                ph[2] = packh2(sb[0], sb[1]);
                ph[3] = packh2(sb[2], sb[3]);

                uint32_t vh[4][4], vl[4][4];
#pragma unroll
                for (int dg = 0; dg < 4; ++dg) {
                    uint32_t off = (((lane & 15) + ks * 16) * ASTR + dg * 16 + (lane >> 4) * 8) * 2;
                    ldmatrix_x4_trans(vh[dg], uVh + off);
                    ldmatrix_x4_trans(vl[dg], uVl + off);
                }
                // term-major PV
#pragma unroll
                for (int dg = 0; dg < 4; ++dg)
#pragma unroll
                    for (int hh = 0; hh < 2; ++hh)
                        mma_16816_f16(o[2 * dg + hh], ph, vh[dg][hh * 2], vh[dg][hh * 2 + 1]);
#pragma unroll
                for (int dg = 0; dg < 4; ++dg)
#pragma unroll
                    for (int hh = 0; hh < 2; ++hh)
                        mma_16816_f16(o[2 * dg + hh], ph, vl[dg][hh * 2], vl[dg][hh * 2 + 1]);
            }

            // deferred row-sum reduction (off the PV critical path)
            rs0 += __shfl_xor_sync(0xffffffffu, rs0, 1);
            rs0 += __shfl_xor_sync(0xffffffffu, rs0, 2);
            rs1 += __shfl_xor_sync(0xffffffffu, rs1, 1);
            rs1 += __shfl_xor_sync(0xffffffffu, rs1, 2);
            l0 = l0 * al0 + rs0;
            l1 = l1 * al1 + rs1;
        }

        // ---- normalize + write Z (single fp16, [B,H,S,Dh] flat) ----
        const float inv0 = 1.f / l0, inv1 = 1.f / l1;
        const int r0 = wid * 16 + (lane >> 2);
        const size_t zr0 = ((size_t)bh * SEQ + (size_t)qb * 128 + r0) * HDIM;
        const size_t zr1 = zr0 + 8 * HDIM;
#pragma unroll
        for (int nt = 0; nt < 8; ++nt) {
            const int c = nt * 8 + (lane & 3) * 2;
            *(uint32_t*)(g_Z + zr0 + c) = packh2(o[nt][0] * inv0, o[nt][1] * inv0);
            *(uint32_t*)(g_Z + zr1 + c) = packh2(o[nt][2] * inv1, o[nt][3] * inv1);
        }
    }
}

// ---------------- launch ----------------
extern "C" void kernel_launch(void* const* d_in, const int* in_sizes, int n_in,
                              void* d_out, int out_size)
{
    const float* X  = (const float*)d_in[0];
    const float* wq = (const float*)d_in[2];
    const float* bq = (const float*)d_in[3];
    const float* wk = (const float*)d_in[4];
    const float* bk = (const float*)d_in[5];
    const float* wv = (const float*)d_in[6];
    const float* bv = (const float*)d_in[7];
    const float* wo = (const float*)d_in[8];
    const float* bo = (const float*)d_in[9];
    float* out = (float*)d_out;

    __nv_bfloat16 *Xhi, *Xlo;
    cudaGetSymbolAddress((void**)&Xhi, g_Xhi);
    cudaGetSymbolAddress((void**)&Xlo, g_Xlo);

    cudaFuncSetAttribute(attn_mma_kernel, cudaFuncAttributeMaxDynamicSharedMemorySize, ATTN_SMEM);
    cudaFuncSetAttribute(qkv_mma_kernel, cudaFuncAttributeMaxDynamicSharedMemorySize, GEMM_SMEM);
    cudaFuncSetAttribute(out_mma_kernel, cudaFuncAttributeMaxDynamicSharedMemorySize, OGEMM_SMEM);

    // split X into bf16 hi/lo; split+transpose 4 weight matrices (wo -> fp16)
    cvt_split_kernel<<<(MROWS * EMB / 4) / 256, 256>>>(X, Xhi, Xlo);
    cvt_splitT_kernel<<<dim3(EMB / 32, EMB / 32, 4), 256>>>(wq, wk, wv, wo);

    // QKV projections (z: 0=Q(xQSCALE,bf16) 1=K(bf16) 2=V(fp16)), per-head layout
    qkv_mma_kernel<<<dim3(EMB / 128, MROWS / 128, 3), 256, GEMM_SMEM>>>(bq, bk, bv);

    // causal flash attention, diagonal-paired -> g_Z (fp16)
    attn_mma_kernel<<<dim3(4, BATCH * HEADS), 256, ATTN_SMEM>>>();

    // output projection: fp16 2-term
    out_mma_kernel<<<dim3(EMB / 128, MROWS / 128), 256, OGEMM_SMEM>>>(bo, out);

    (void)in_sizes; (void)n_in; (void)out_size;
}

// round 12
// speedup vs baseline: 3.1785x; 1.0032x over previous
#include <cuda_runtime.h>
#include <cuda_bf16.h>
#include <cuda_fp16.h>
#include <cstdint>

// Problem constants
#define BATCH   4
#define SEQ     1024
#define EMB     1024
#define HEADS   16
#define HDIM    64
#define MROWS   (BATCH * SEQ)      // 4096

// ---------------- scratch (16B-aligned for cp.async) ----------------
__device__ __align__(256) __nv_bfloat16 g_Xhi[MROWS * EMB];
__device__ __align__(256) __nv_bfloat16 g_Xlo[MROWS * EMB];
// Q/K in per-head layout [B, H, S, HDIM], bf16 hi/lo; V fp16 hi/lo
__device__ __align__(256) __nv_bfloat16 g_Qhi[MROWS * EMB];
__device__ __align__(256) __nv_bfloat16 g_Qlo[MROWS * EMB];
__device__ __align__(256) __nv_bfloat16 g_Khi[MROWS * EMB];
__device__ __align__(256) __nv_bfloat16 g_Klo[MROWS * EMB];
__device__ __align__(256) __half       g_Vhi[MROWS * EMB];
__device__ __align__(256) __half       g_Vlo[MROWS * EMB];
// Z single fp16 ([B,H,S,Dh] flat = [MROWS, EMB] row-major view)
__device__ __align__(256) __half       g_Z[MROWS * EMB];
// wq,wk,wv transposed [N,K] bf16 hi/lo; wo transposed [N,K] fp16 hi/lo
__device__ __align__(256) __nv_bfloat16 g_Whi[3 * EMB * EMB];
__device__ __align__(256) __nv_bfloat16 g_Wlo[3 * EMB * EMB];
__device__ __align__(256) __half       g_WOhi[EMB * EMB];
__device__ __align__(256) __half       g_WOlo[EMB * EMB];

// ================= PTX helpers (sm_80+ subset only) =============
__device__ __forceinline__ uint32_t smem_u32(const void* p) {
    uint32_t a;
    asm("{ .reg .u64 t; cvta.to.shared.u64 t, %1; cvt.u32.u64 %0, t; }" : "=r"(a) : "l"(p));
    return a;
}

__device__ __forceinline__ void cp_async16(uint32_t saddr, const void* gaddr) {
    asm volatile("cp.async.cg.shared.global [%0], [%1], 16;" :: "r"(saddr), "l"(gaddr));
}
#define CP_COMMIT()  asm volatile("cp.async.commit_group;" ::: "memory")
template <int N>
__device__ __forceinline__ void cp_wait() {
    asm volatile("cp.async.wait_group %0;" :: "n"(N) : "memory");
}

#define BAR_ARRIVE(id, cnt) \
    asm volatile("bar.arrive %0, %1;" :: "r"((int)(id)), "r"((int)(cnt)) : "memory")
#define BAR_SYNC_N(id, cnt) \
    asm volatile("bar.sync %0, %1;" :: "r"((int)(id)), "r"((int)(cnt)) : "memory")

__device__ __forceinline__ void ldmatrix_x4(uint32_t (&r)[4], uint32_t addr) {
    asm volatile("ldmatrix.sync.aligned.m8n8.x4.shared.b16 {%0,%1,%2,%3}, [%4];"
                 : "=r"(r[0]), "=r"(r[1]), "=r"(r[2]), "=r"(r[3]) : "r"(addr));
}
__device__ __forceinline__ void ldmatrix_x4_trans(uint32_t (&r)[4], uint32_t addr) {
    asm volatile("ldmatrix.sync.aligned.m8n8.x4.trans.shared.b16 {%0,%1,%2,%3}, [%4];"
                 : "=r"(r[0]), "=r"(r[1]), "=r"(r[2]), "=r"(r[3]) : "r"(addr));
}

__device__ __forceinline__ void mma_16816(float (&d)[4], const uint32_t (&a)[4],
                                          uint32_t b0, uint32_t b1) {
    asm volatile(
        "mma.sync.aligned.m16n8k16.row.col.f32.bf16.bf16.f32 "
        "{%0,%1,%2,%3}, {%4,%5,%6,%7}, {%8,%9}, {%0,%1,%2,%3};"
        : "+f"(d[0]), "+f"(d[1]), "+f"(d[2]), "+f"(d[3])
        : "r"(a[0]), "r"(a[1]), "r"(a[2]), "r"(a[3]), "r"(b0), "r"(b1));
}
__device__ __forceinline__ void mma_16816_f16(float (&d)[4], const uint32_t (&a)[4],
                                              uint32_t b0, uint32_t b1) {
    asm volatile(
        "mma.sync.aligned.m16n8k16.row.col.f32.f16.f16.f32 "
        "{%0,%1,%2,%3}, {%4,%5,%6,%7}, {%8,%9}, {%0,%1,%2,%3};"
        : "+f"(d[0]), "+f"(d[1]), "+f"(d[2]), "+f"(d[3])
        : "r"(a[0]), "r"(a[1]), "r"(a[2]), "r"(a[3]), "r"(b0), "r"(b1));
}

// fp32 pair -> packed bf16x2 hi + lo
__device__ __forceinline__ void split2(float x, float y, uint32_t& hi, uint32_t& lo) {
    __nv_bfloat16 hx = __float2bfloat16(x);
    __nv_bfloat16 hy = __float2bfloat16(y);
    __nv_bfloat16 lx = __float2bfloat16(x - __bfloat162float(hx));
    __nv_bfloat16 ly = __float2bfloat16(y - __bfloat162float(hy));
    __nv_bfloat162 hp(hx, hy), lp(lx, ly);
    hi = *(uint32_t*)&hp;
    lo = *(uint32_t*)&lp;
}
// fp32 pair -> packed fp16x2 hi + lo
__device__ __forceinline__ void split2h(float x, float y, uint32_t& hi, uint32_t& lo) {
    __half hx = __float2half_rn(x);
    __half hy = __float2half_rn(y);
    __half lx = __float2half_rn(x - __half2float(hx));
    __half ly = __float2half_rn(y - __half2float(hy));
    __half2 hp(hx, hy), lp(lx, ly);
    hi = *(uint32_t*)&hp;
    lo = *(uint32_t*)&lp;
}
__device__ __forceinline__ uint32_t packh2(float x, float y) {
    __half2 h = __floats2half2_rn(x, y);
    return *(uint32_t*)&h;
}

// ================= conversion kernels =================
__global__ __launch_bounds__(256) void cvt_split_kernel(
    const float* __restrict__ src, __nv_bfloat16* __restrict__ hi,
    __nv_bfloat16* __restrict__ lo)
{
    int i = blockIdx.x * blockDim.x + threadIdx.x;     // one float4 each
    float4 v = ((const float4*)src)[i];
    uint32_t h0, l0, h1, l1;
    split2(v.x, v.y, h0, l0);
    split2(v.z, v.w, h1, l1);
    ((uint2*)hi)[i] = make_uint2(h0, h1);
    ((uint2*)lo)[i] = make_uint2(l0, l1);
}

// W [K,N] fp32 -> WT [N,K] hi/lo (transpose+split). z<3: bf16; z==3: fp16.
__global__ __launch_bounds__(256) void cvt_splitT_kernel(
    const float* __restrict__ w0, const float* __restrict__ w1,
    const float* __restrict__ w2, const float* __restrict__ w3)
{
    __shared__ float t[32][33];
    const int z = blockIdx.z;
    const float* W = (z == 0) ? w0 : (z == 1) ? w1 : (z == 2) ? w2 : w3;
    const int bx = blockIdx.x * 32;   // N base
    const int by = blockIdx.y * 32;   // K base
    const int tx = threadIdx.x & 31;
    const int ty = threadIdx.x >> 5;  // 0..7
    for (int i = ty; i < 32; i += 8)
        t[i][tx] = W[(size_t)(by + i) * EMB + bx + tx];
    __syncthreads();
    if (z < 3) {
        __nv_bfloat16* hiT = g_Whi + (size_t)z * EMB * EMB;
        __nv_bfloat16* loT = g_Wlo + (size_t)z * EMB * EMB;
        for (int i = ty; i < 32; i += 8) {
            float v = t[tx][i];
            __nv_bfloat16 h = __float2bfloat16(v);
            __nv_bfloat16 l = __float2bfloat16(v - __bfloat162float(h));
            hiT[(size_t)(bx + i) * EMB + by + tx] = h;
            loT[(size_t)(bx + i) * EMB + by + tx] = l;
        }
    } else {
        for (int i = ty; i < 32; i += 8) {
            float v = t[tx][i];
            __half h = __float2half_rn(v);
            __half l = __float2half_rn(v - __half2float(h));
            g_WOhi[(size_t)(bx + i) * EMB + by + tx] = h;
            g_WOlo[(size_t)(bx + i) * EMB + by + tx] = l;
        }
    }
}

// ================= HMMA bf16x3 QKV GEMM =================
#define BK          32
#define NCHUNK      (EMB / BK)              // 32
#define SA          40                       // smem row stride (elems)
#define SPLIT_BYTES (128 * SA * 2)          // 10240
#define STAGE_BYTES (4 * SPLIT_BYTES)       // 40960
#define GEMM_SMEM   (2 * STAGE_BYTES)       // 81920

// Q pre-scale: 1/16^0.25 * log2(e)  (softmax done in exp2 domain)
#define QSCALE (0.5f * 1.4426950408889634f)

__device__ __forceinline__ void load_stage_async(
    uint32_t smb, const __nv_bfloat16* __restrict__ Ahi, const __nv_bfloat16* __restrict__ Alo,
    const __nv_bfloat16* __restrict__ Bhi, const __nv_bfloat16* __restrict__ Blo,
    int mbase, int nbase, int k0, int buf, int tid)
{
    const __nv_bfloat16* gsrc[4] = {
        Ahi + (size_t)mbase * EMB + k0, Alo + (size_t)mbase * EMB + k0,
        Bhi + (size_t)nbase * EMB + k0, Blo + (size_t)nbase * EMB + k0 };
    const uint32_t sbase = smb + buf * STAGE_BYTES;
#pragma unroll
    for (int m = 0; m < 4; ++m) {
#pragma unroll
        for (int i = 0; i < 2; ++i) {
            int idx = tid + i * 256;
            int r = idx >> 2, seg = idx & 3;
            uint32_t sa = sbase + m * SPLIT_BYTES + (r * SA + seg * 8) * 2;
            cp_async16(sa, gsrc[m] + (size_t)r * EMB + seg * 8);
        }
    }
}

// mode 0: Q (bf16 split, xQSCALE); mode 1: K (bf16 split); mode 2: V (fp16 split)
__global__ __launch_bounds__(256, 2)
void qkv_mma_kernel(const float* __restrict__ bq, const float* __restrict__ bk,
                    const float* __restrict__ bv)
{
    extern __shared__ char sm[];
    const uint32_t smb = smem_u32(sm);
    const int tid  = threadIdx.x;
    const int wid  = tid >> 5;
    const int lane = tid & 31;
    const int mbase = blockIdx.y * 128;
    const int nbase = blockIdx.x * 128;
    const int mode = blockIdx.z;

    const __nv_bfloat16* Bh = g_Whi + (size_t)mode * EMB * EMB;
    const __nv_bfloat16* Bl = g_Wlo + (size_t)mode * EMB * EMB;
    const float* bias = (mode == 0) ? bq : (mode == 1) ? bk : bv;

    const int wm = (wid & 1) * 64;
    const int wn = (wid >> 1) * 32;

    float acc[4][4][4];
#pragma unroll
    for (int mi = 0; mi < 4; ++mi)
#pragma unroll
        for (int ni = 0; ni < 4; ++ni)
#pragma unroll
            for (int e = 0; e < 4; ++e) acc[mi][ni][e] = 0.f;

    const int a_row = (lane & 15);
    const int a_koff = (lane >> 4) * 8;
    const int b_row = (lane & 7) + ((lane >> 4) * 8);
    const int b_koff = ((lane >> 3) & 1) * 8;

    load_stage_async(smb, g_Xhi, g_Xlo, Bh, Bl, mbase, nbase, 0, 0, tid);
    CP_COMMIT();

    for (int ck = 0; ck < NCHUNK; ++ck) {
        const int buf = ck & 1;
        cp_wait<0>();
        __syncthreads();
        if (ck + 1 < NCHUNK) {
            load_stage_async(smb, g_Xhi, g_Xlo, Bh, Bl, mbase, nbase, (ck + 1) * BK, buf ^ 1, tid);
            CP_COMMIT();
        }

        const uint32_t sAhi = smb + buf * STAGE_BYTES;
        const uint32_t sAlo = sAhi + SPLIT_BYTES;
        const uint32_t sBhi = sAhi + 2 * SPLIT_BYTES;
        const uint32_t sBlo = sAhi + 3 * SPLIT_BYTES;

#pragma unroll
        for (int ks = 0; ks < 2; ++ks) {
            const int k0 = ks * 16;
            uint32_t ahi[4][4], alo[4][4];
#pragma unroll
            for (int mi = 0; mi < 4; ++mi) {
                uint32_t off = ((wm + mi * 16 + a_row) * SA + k0 + a_koff) * 2;
                ldmatrix_x4(ahi[mi], sAhi + off);
                ldmatrix_x4(alo[mi], sAlo + off);
            }
            uint32_t bhi[2][4], blo[2][4];
#pragma unroll
            for (int bi = 0; bi < 2; ++bi) {
                uint32_t off = ((wn + bi * 16 + b_row) * SA + k0 + b_koff) * 2;
                ldmatrix_x4(bhi[bi], sBhi + off);
                ldmatrix_x4(blo[bi], sBlo + off);
            }
#pragma unroll
            for (int mi = 0; mi < 4; ++mi)
#pragma unroll
                for (int ni = 0; ni < 4; ++ni) {
                    const int g = ni >> 1, h = (ni & 1) * 2;
                    mma_16816(acc[mi][ni], ahi[mi], bhi[g][h], bhi[g][h + 1]);
                }
#pragma unroll
            for (int mi = 0; mi < 4; ++mi)
#pragma unroll
                for (int ni = 0; ni < 4; ++ni) {
                    const int g = ni >> 1, h = (ni & 1) * 2;
                    mma_16816(acc[mi][ni], ahi[mi], blo[g][h], blo[g][h + 1]);
                }
#pragma unroll
            for (int mi = 0; mi < 4; ++mi)
#pragma unroll
                for (int ni = 0; ni < 4; ++ni) {
                    const int g = ni >> 1, h = (ni & 1) * 2;
                    mma_16816(acc[mi][ni], alo[mi], bhi[g][h], bhi[g][h + 1]);
                }
        }
    }

    const int fr = lane >> 2;
    const int fc = (lane & 3) * 2;
    const float qscale = (mode == 0) ? QSCALE : 1.0f;
#pragma unroll
    for (int mi = 0; mi < 4; ++mi) {
#pragma unroll
        for (int ni = 0; ni < 4; ++ni) {
            const int col = nbase + wn + ni * 8 + fc;
            const float b0 = bias[col], b1 = bias[col + 1];
            const int row0 = mbase + wm + mi * 16 + fr;
            const float v0 = (acc[mi][ni][0] + b0) * qscale;
            const float v1 = (acc[mi][ni][1] + b1) * qscale;
            const float v2 = (acc[mi][ni][2] + b0) * qscale;
            const float v3 = (acc[mi][ni][3] + b1) * qscale;
            // per-head layout: row0 = b*1024 + s ; col = h*64 + d
            const int bb = row0 >> 10, ss = row0 & 1023;
            const int hh = col >> 6,  dd = col & 63;
            const size_t dst = (((size_t)bb * HEADS + hh) * SEQ + ss) * HDIM + dd;
            if (mode == 2) {
                uint32_t h01, l01, h23, l23;
                split2h(v0, v1, h01, l01);
                split2h(v2, v3, h23, l23);
                *(uint32_t*)(g_Vhi + dst)            = h01;
                *(uint32_t*)(g_Vlo + dst)            = l01;
                *(uint32_t*)(g_Vhi + dst + 8 * HDIM) = h23;
                *(uint32_t*)(g_Vlo + dst + 8 * HDIM) = l23;
            } else {
                __nv_bfloat16* Chi = (mode == 0) ? g_Qhi : g_Khi;
                __nv_bfloat16* Clo = (mode == 0) ? g_Qlo : g_Klo;
                uint32_t h01, l01, h23, l23;
                split2(v0, v1, h01, l01);
                split2(v2, v3, h23, l23);
                *(uint32_t*)(Chi + dst)            = h01;
                *(uint32_t*)(Clo + dst)            = l01;
                *(uint32_t*)(Chi + dst + 8 * HDIM) = h23;
                *(uint32_t*)(Clo + dst + 8 * HDIM) = l23;
            }
        }
    }
}

// ================= out projection: fp16 2-term (Z single, Wo hi/lo) ========
#define OSTAGE_BYTES (3 * SPLIT_BYTES)       // 30720: A, Bhi, Blo
#define OGEMM_SMEM   (2 * OSTAGE_BYTES)      // 61440

__device__ __forceinline__ void load_stage_out(
    uint32_t smb, int mbase, int nbase, int k0, int buf, int tid)
{
    const __half* gsrc[3] = {
        g_Z    + (size_t)mbase * EMB + k0,
        g_WOhi + (size_t)nbase * EMB + k0,
        g_WOlo + (size_t)nbase * EMB + k0 };
    const uint32_t sbase = smb + buf * OSTAGE_BYTES;
#pragma unroll
    for (int m = 0; m < 3; ++m) {
#pragma unroll
        for (int i = 0; i < 2; ++i) {
            int idx = tid + i * 256;
            int r = idx >> 2, seg = idx & 3;
            uint32_t sa = sbase + m * SPLIT_BYTES + (r * SA + seg * 8) * 2;
            cp_async16(sa, gsrc[m] + (size_t)r * EMB + seg * 8);
        }
    }
}

__global__ __launch_bounds__(256, 2)
void out_mma_kernel(const float* __restrict__ bo, float* __restrict__ out)
{
    extern __shared__ char sm[];
    const uint32_t smb = smem_u32(sm);
    const int tid  = threadIdx.x;
    const int wid  = tid >> 5;
    const int lane = tid & 31;
    const int mbase = blockIdx.y * 128;
    const int nbase = blockIdx.x * 128;

    const int wm = (wid & 1) * 64;
    const int wn = (wid >> 1) * 32;

    float acc[4][4][4];
#pragma unroll
    for (int mi = 0; mi < 4; ++mi)
#pragma unroll
        for (int ni = 0; ni < 4; ++ni)
#pragma unroll
            for (int e = 0; e < 4; ++e) acc[mi][ni][e] = 0.f;

    const int a_row = (lane & 15);
    const int a_koff = (lane >> 4) * 8;
    const int b_row = (lane & 7) + ((lane >> 4) * 8);
    const int b_koff = ((lane >> 3) & 1) * 8;

    load_stage_out(smb, mbase, nbase, 0, 0, tid);
    CP_COMMIT();

    for (int ck = 0; ck < NCHUNK; ++ck) {
        const int buf = ck & 1;
        cp_wait<0>();
        __syncthreads();
        if (ck + 1 < NCHUNK) {
            load_stage_out(smb, mbase, nbase, (ck + 1) * BK, buf ^ 1, tid);
            CP_COMMIT();
        }

        const uint32_t sA   = smb + buf * OSTAGE_BYTES;
        const uint32_t sBhi = sA + SPLIT_BYTES;
        const uint32_t sBlo = sA + 2 * SPLIT_BYTES;

#pragma unroll
        for (int ks = 0; ks < 2; ++ks) {
            const int k0 = ks * 16;
            uint32_t a[4][4];
#pragma unroll
            for (int mi = 0; mi < 4; ++mi) {
                uint32_t off = ((wm + mi * 16 + a_row) * SA + k0 + a_koff) * 2;
                ldmatrix_x4(a[mi], sA + off);
            }
            uint32_t bhi[2][4], blo[2][4];
#pragma unroll
            for (int bi = 0; bi < 2; ++bi) {
                uint32_t off = ((wn + bi * 16 + b_row) * SA + k0 + b_koff) * 2;
                ldmatrix_x4(bhi[bi], sBhi + off);
                ldmatrix_x4(blo[bi], sBlo + off);
            }
#pragma unroll
            for (int mi = 0; mi < 4; ++mi)
#pragma unroll
                for (int ni = 0; ni < 4; ++ni) {
                    const int g = ni >> 1, h = (ni & 1) * 2;
                    mma_16816_f16(acc[mi][ni], a[mi], bhi[g][h], bhi[g][h + 1]);
                }
#pragma unroll
            for (int mi = 0; mi < 4; ++mi)
#pragma unroll
                for (int ni = 0; ni < 4; ++ni) {
                    const int g = ni >> 1, h = (ni & 1) * 2;
                    mma_16816_f16(acc[mi][ni], a[mi], blo[g][h], blo[g][h + 1]);
                }
        }
    }

    const int fr = lane >> 2;
    const int fc = (lane & 3) * 2;
#pragma unroll
    for (int mi = 0; mi < 4; ++mi) {
#pragma unroll
        for (int ni = 0; ni < 4; ++ni) {
            const int col = nbase + wn + ni * 8 + fc;
            const float b0 = bo[col], b1 = bo[col + 1];
            const int row0 = mbase + wm + mi * 16 + fr;
            float* p0 = out + (size_t)row0 * EMB + col;
            float* p1 = out + (size_t)(row0 + 8) * EMB + col;
            p0[0] = acc[mi][ni][0] + b0;
            p0[1] = acc[mi][ni][1] + b1;
            p1[0] = acc[mi][ni][2] + b0;
            p1[1] = acc[mi][ni][3] + b1;
        }
    }
}

// ================= Flash attention via HMMA (producer/consumer) =============
// Br=128, Bc=64, diagonal-paired: CTA p handles q-tiles {7-p, p}; 18 KV tiles.
// NO mbarriers: FULL(b) = named barrier (loader arrives after cp_wait proves
// the tile landed; consumers sync). EMPTY(b) = named barrier (consumers
// arrive after reading; loader syncs before overwrite). 320 = 256 + 64.
#define ASTR 72
#define Q_BYTES    (128 * ASTR * 2)          // 18432 per split
#define KVBUF      (4 * 64 * ASTR * 2)       // 36864: Kh,Kl,Vh,Vl
#define ATTN_SMEM  (2 * Q_BYTES + 2 * KVBUF) // 110592
#define ATTN_G     18
#define BARCNT     320
#define NBAR_E0    1
#define NBAR_E1    2
#define NBAR_F0    3
#define NBAR_F1    4

// KV tile load by 64 threads (warps 0-1): tid64 in [0,64)
__device__ __forceinline__ void attn_load_kv64(uint32_t kvbase, size_t gbase,
                                               int jb, int tid64)
{
#pragma unroll
    for (int i = 0; i < 8; ++i) {
        int idx = tid64 + i * 64;                // 0..511
        int r = idx >> 3, seg = idx & 7;
        const size_t g = gbase + (size_t)(jb * 64 + r) * HDIM + seg * 8;
        const uint32_t so = (r * ASTR + seg * 8) * 2;
        cp_async16(kvbase + so,                  g_Khi + g);
        cp_async16(kvbase + 64 * ASTR * 2 + so,  g_Klo + g);
        cp_async16(kvbase + 128 * ASTR * 2 + so, g_Vhi + g);
        cp_async16(kvbase + 192 * ASTR * 2 + so, g_Vlo + g);
    }
}

// Q tile load by all 256 threads
__device__ __forceinline__ void attn_load_q(uint32_t uQh, uint32_t uQl,
                                            size_t gbase, int qb, int tid)
{
#pragma unroll
    for (int i = 0; i < 4; ++i) {
        int idx = tid + i * 256;
        int r = idx >> 3, seg = idx & 7;
        const size_t g = gbase + (size_t)(qb * 128 + r) * HDIM + seg * 8;
        const uint32_t so = (r * ASTR + seg * 8) * 2;
        cp_async16(uQh + so, g_Qhi + g);
        cp_async16(uQl + so, g_Qlo + g);
    }
}

__global__ __launch_bounds__(256, 2) void attn_mma_kernel()
{
    extern __shared__ char smraw[];
    const uint32_t uQh  = smem_u32(smraw);
    const uint32_t uQl  = uQh + Q_BYTES;
    const uint32_t uKV0 = uQl + Q_BYTES;

    const int tid = threadIdx.x, wid = tid >> 5, lane = tid & 31;
    const int pp = blockIdx.x;               // 0..3 (pair index)
    const int bh = blockIdx.y;               // 0..63
    const size_t gbase = (size_t)bh * SEQ * HDIM;
    const int qa = 7 - pp;
    const int cb = 2 * qa + 2;               // tiles consumed by first q-tile

    attn_load_q(uQh, uQl, gbase, qa, tid);
    CP_COMMIT();
    cp_wait<0>();
    __syncthreads();                         // Q visible

    // prologue: loaders issue tiles 0,1; prove tile0 landed; signal FULL0
    if (wid < 2) {
        attn_load_kv64(uKV0, gbase, 0, tid);
        CP_COMMIT();
        attn_load_kv64(uKV0 + KVBUF, gbase, 1, tid);
        CP_COMMIT();
        cp_wait<1>();                        // tile 0 complete (tile 1 in flight)
        BAR_ARRIVE(NBAR_F0, BARCNT);
    }

    float o[8][4];
#pragma unroll
    for (int nt = 0; nt < 8; ++nt)
#pragma unroll
        for (int e = 0; e < 4; ++e) o[nt][e] = 0.f;
    float m0 = -1e30f, m1 = -1e30f, l0 = 0.f, l1 = 0.f;

    int qb = qa;
    int r0g = qb * 128 + wid * 16 + (lane >> 2);

    const int a_row = lane & 15;
    const int a_koff = (lane >> 4) * 8;
    const int b_row = (lane & 7) + ((lane >> 4) * 8);
    const int b_koff = ((lane >> 3) & 1) * 8;

    for (int c = 0; c < ATTN_G; ++c) {
        if (c == cb) {
            // write out first tile, reset, reload Q for second tile
            const float i0 = 1.f / l0, i1 = 1.f / l1;
            const int r0 = wid * 16 + (lane >> 2);
            const size_t zr0 = ((size_t)bh * SEQ + (size_t)qb * 128 + r0) * HDIM;
#pragma unroll
            for (int nt = 0; nt < 8; ++nt) {
                const int cc = nt * 8 + (lane & 3) * 2;
                *(uint32_t*)(g_Z + zr0 + cc) = packh2(o[nt][0] * i0, o[nt][1] * i0);
                *(uint32_t*)(g_Z + zr0 + 8 * HDIM + cc) = packh2(o[nt][2] * i1, o[nt][3] * i1);
            }
#pragma unroll
            for (int nt = 0; nt < 8; ++nt)
#pragma unroll
                for (int e = 0; e < 4; ++e) o[nt][e] = 0.f;
            m0 = -1e30f; m1 = -1e30f; l0 = 0.f; l1 = 0.f;
            qb = pp;
            r0g = qb * 128 + wid * 16 + (lane >> 2);
            __syncthreads();                 // everyone done with old Q
            attn_load_q(uQh, uQl, gbase, qb, tid);
            CP_COMMIT();
            cp_wait<0>();                    // drains Q (and any loader KV groups — safe)
            __syncthreads();                 // new Q visible
        }

        // wait KV tile c full (64 loader arrivals + 256 syncs = 320)
        BAR_SYNC_N((c & 1) ? NBAR_F1 : NBAR_F0, BARCNT);
        const uint32_t kvb = uKV0 + (c & 1) * KVBUF;
        const uint32_t uKh = kvb;
        const uint32_t uKl = kvb + 64 * ASTR * 2;
        const uint32_t uVh = kvb + 128 * ASTR * 2;
        const uint32_t uVl = kvb + 192 * ASTR * 2;
        const int jb = (c < cb) ? c : c - cb;

        // ---- S = Q @ K^T (bf16 3-term; Q pre-scaled by QSCALE) ----
        float s[8][4];
#pragma unroll
        for (int nt = 0; nt < 8; ++nt)
#pragma unroll
            for (int e = 0; e < 4; ++e) s[nt][e] = 0.f;

#pragma unroll
        for (int ks = 0; ks < 4; ++ks) {
            uint32_t qh[4], ql[4];
            {
                uint32_t off = ((wid * 16 + a_row) * ASTR + ks * 16 + a_koff) * 2;
                ldmatrix_x4(qh, uQh + off);
                ldmatrix_x4(ql, uQl + off);
            }
            uint32_t kh[4][4], kl[4][4];
#pragma unroll
            for (int g = 0; g < 4; ++g) {
                uint32_t off = ((g * 16 + b_row) * ASTR + ks * 16 + b_koff) * 2;
                ldmatrix_x4(kh[g], uKh + off);
                ldmatrix_x4(kl[g], uKl + off);
            }
#pragma unroll
            for (int g = 0; g < 4; ++g)
#pragma unroll
                for (int hh = 0; hh < 2; ++hh)
                    mma_16816(s[2 * g + hh], qh, kh[g][hh * 2], kh[g][hh * 2 + 1]);
#pragma unroll
            for (int g = 0; g < 4; ++g)
#pragma unroll
                for (int hh = 0; hh < 2; ++hh)
                    mma_16816(s[2 * g + hh], qh, kl[g][hh * 2], kl[g][hh * 2 + 1]);
#pragma unroll
            for (int g = 0; g < 4; ++g)
#pragma unroll
                for (int hh = 0; hh < 2; ++hh)
                    mma_16816(s[2 * g + hh], ql, kh[g][hh * 2], kh[g][hh * 2 + 1]);
        }

        // ---- causal mask + online softmax in exp2 domain ----
        const bool needmask = (jb >= 2 * qb);
        float mx0 = -1e30f, mx1 = -1e30f;
#pragma unroll
        for (int nt = 0; nt < 8; ++nt) {
            if (needmask) {
                const int cc = jb * 64 + nt * 8 + (lane & 3) * 2;
                s[nt][0] = (cc     <= r0g)     ? s[nt][0] : -1e30f;
                s[nt][1] = (cc + 1 <= r0g)     ? s[nt][1] : -1e30f;
                s[nt][2] = (cc     <= r0g + 8) ? s[nt][2] : -1e30f;
                s[nt][3] = (cc + 1 <= r0g + 8) ? s[nt][3] : -1e30f;
            }
            mx0 = fmaxf(mx0, fmaxf(s[nt][0], s[nt][1]));
            mx1 = fmaxf(mx1, fmaxf(s[nt][2], s[nt][3]));
        }
        mx0 = fmaxf(mx0, __shfl_xor_sync(0xffffffffu, mx0, 1));
        mx0 = fmaxf(mx0, __shfl_xor_sync(0xffffffffu, mx0, 2));
        mx1 = fmaxf(mx1, __shfl_xor_sync(0xffffffffu, mx1, 1));
        mx1 = fmaxf(mx1, __shfl_xor_sync(0xffffffffu, mx1, 2));

        const float nm0 = fmaxf(m0, mx0), nm1 = fmaxf(m1, mx1);
        const float al0 = exp2f(m0 - nm0), al1 = exp2f(m1 - nm1);
        m0 = nm0; m1 = nm1;

#pragma unroll
        for (int nt = 0; nt < 8; ++nt) {
            o[nt][0] *= al0; o[nt][1] *= al0;
            o[nt][2] *= al1; o[nt][3] *= al1;
        }

        // ---- per-ks: exp2 + pack + PV (P fp16 single; V fp16 hi/lo) ----
        float rs0 = 0.f, rs1 = 0.f;
#pragma unroll
        for (int ks = 0; ks < 4; ++ks) {
            float* sa = s[2 * ks];
            float* sb = s[2 * ks + 1];
            sa[0] = exp2f(sa[0] - m0);
            sa[1] = exp2f(sa[1] - m0);
            sa[2] = exp2f(sa[2] - m1);
            sa[3] = exp2f(sa[3] - m1);
            sb[0] = exp2f(sb[0] - m0);
            sb[1] = exp2f(sb[1] - m0);
            sb[2] = exp2f(sb[2] - m1);
            sb[3] = exp2f(sb[3] - m1);
            rs0 += sa[0] + sa[1] + sb[0] + sb[1];
            rs1 += sa[2] + sa[3] + sb[2] + sb[3];

            uint32_t ph[4];
            ph[0] = packh2(sa[0], sa[1]);
            ph[1] = packh2(sa[2], sa[3]);
            ph[2] = packh2(sb[0], sb[1]);
            ph[3] = packh2(sb[2], sb[3]);

            uint32_t vh[4][4], vl[4][4];
#pragma unroll
            for (int dg = 0; dg < 4; ++dg) {
                uint32_t off = (((lane & 15) + ks * 16) * ASTR + dg * 16 + (lane >> 4) * 8) * 2;
                ldmatrix_x4_trans(vh[dg], uVh + off);
                ldmatrix_x4_trans(vl[dg], uVl + off);
            }
#pragma unroll
            for (int dg = 0; dg < 4; ++dg)
#pragma unroll
                for (int hh = 0; hh < 2; ++hh)
                    mma_16816_f16(o[2 * dg + hh], ph, vh[dg][hh * 2], vh[dg][hh * 2 + 1]);
#pragma unroll
            for (int dg = 0; dg < 4; ++dg)
#pragma unroll
                for (int hh = 0; hh < 2; ++hh)
                    mma_16816_f16(o[2 * dg + hh], ph, vl[dg][hh * 2], vl[dg][hh * 2 + 1]);
        }

        // done reading buffer c&1
        BAR_ARRIVE((c & 1) ? NBAR_E1 : NBAR_E0, BARCNT);

        // loader: refill buffer (c&1) with tile c+2; signal FULL for tile c+1
        if (wid < 2) {
            const bool refill = (c + 2 < ATTN_G);
            if (refill) {
                BAR_SYNC_N((c & 1) ? NBAR_E1 : NBAR_E0, BARCNT);
                const int g = c + 2;
                const int gj = (g < cb) ? g : g - cb;
                attn_load_kv64(uKV0 + (g & 1) * KVBUF, gbase, gj, tid);
                CP_COMMIT();
            }
            if (c + 1 < ATTN_G) {
                if (refill) cp_wait<1>();    // tile c+1 done (c+2 in flight)
                else        cp_wait<0>();    // tile c+1 done (nothing else pending)
                BAR_ARRIVE(((c + 1) & 1) ? NBAR_F1 : NBAR_F0, BARCNT);
            }
        }

        // deferred row-sum reduction
        rs0 += __shfl_xor_sync(0xffffffffu, rs0, 1);
        rs0 += __shfl_xor_sync(0xffffffffu, rs0, 2);
        rs1 += __shfl_xor_sync(0xffffffffu, rs1, 1);
        rs1 += __shfl_xor_sync(0xffffffffu, rs1, 2);
        l0 = l0 * al0 + rs0;
        l1 = l1 * al1 + rs1;
    }

    // ---- final write out (second tile, qb == pp) ----
    const float inv0 = 1.f / l0, inv1 = 1.f / l1;
    const int r0 = wid * 16 + (lane >> 2);
    const size_t zr0 = ((size_t)bh * SEQ + (size_t)qb * 128 + r0) * HDIM;
#pragma unroll
    for (int nt = 0; nt < 8; ++nt) {
        const int cc = nt * 8 + (lane & 3) * 2;
        *(uint32_t*)(g_Z + zr0 + cc) = packh2(o[nt][0] * inv0, o[nt][1] * inv0);
        *(uint32_t*)(g_Z + zr0 + 8 * HDIM + cc) = packh2(o[nt][2] * inv1, o[nt][3] * inv1);
    }
}

// ---------------- launch ----------------
extern "C" void kernel_launch(void* const* d_in, const int* in_sizes, int n_in,
                              void* d_out, int out_size)
{
    const float* X  = (const float*)d_in[0];
    const float* wq = (const float*)d_in[2];
    const float* bq = (const float*)d_in[3];
    const float* wk = (const float*)d_in[4];
    const float* bk = (const float*)d_in[5];
    const float* wv = (const float*)d_in[6];
    const float* bv = (const float*)d_in[7];
    const float* wo = (const float*)d_in[8];
    const float* bo = (const float*)d_in[9];
    float* out = (float*)d_out;

    __nv_bfloat16 *Xhi, *Xlo;
    cudaGetSymbolAddress((void**)&Xhi, g_Xhi);
    cudaGetSymbolAddress((void**)&Xlo, g_Xlo);

    cudaFuncSetAttribute(attn_mma_kernel, cudaFuncAttributeMaxDynamicSharedMemorySize, ATTN_SMEM);
    cudaFuncSetAttribute(qkv_mma_kernel, cudaFuncAttributeMaxDynamicSharedMemorySize, GEMM_SMEM);
    cudaFuncSetAttribute(out_mma_kernel, cudaFuncAttributeMaxDynamicSharedMemorySize, OGEMM_SMEM);

    // split X into bf16 hi/lo; split+transpose 4 weight matrices (wo -> fp16)
    cvt_split_kernel<<<(MROWS * EMB / 4) / 256, 256>>>(X, Xhi, Xlo);
    cvt_splitT_kernel<<<dim3(EMB / 32, EMB / 32, 4), 256>>>(wq, wk, wv, wo);

    // QKV projections (z: 0=Q(xQSCALE,bf16) 1=K(bf16) 2=V(fp16)), per-head layout
    qkv_mma_kernel<<<dim3(EMB / 128, MROWS / 128, 3), 256, GEMM_SMEM>>>(bq, bk, bv);

    // causal flash attention, diagonal-paired, producer/consumer -> g_Z (fp16)
    attn_mma_kernel<<<dim3(4, BATCH * HEADS), 256, ATTN_SMEM>>>();

    // output projection: fp16 2-term
    out_mma_kernel<<<dim3(EMB / 128, MROWS / 128), 256, OGEMM_SMEM>>>(bo, out);

    (void)in_sizes; (void)n_in; (void)out_size;
}